// round 13
// baseline (speedup 1.0000x reference)
#include <cuda_runtime.h>
#include <cuda_bf16.h>
#include <cstdint>

// ---------------- problem constants ----------------
#define BATCH   128
#define LTOT    720
#define FEAT    128
#define SEGL    24
#define WINN    15
#define NPREDK  4
#define DDIM    128
#define HDIM    512
#define NROWS   (BATCH*FEAT)          // 16384
#define MTOT    (NPREDK*NROWS)        // 65536
#define EPSC    1e-6f
#define EPS2    1e-12f
#define MAXNC   0.99999f
#define CLIPC   0.99999988f
#define DECAYF  0.9f

// global scratch (static __device__, no allocs)
__device__ float g_z[(size_t)WINN * NROWS * DDIM];                  // window z
__device__ float g_zn[(size_t)WINN * NROWS];                        // ||z||^2
__device__ __align__(16) __nv_bfloat16 g_Ah[(size_t)MTOT * DDIM];   // MLP A hi
__device__ __align__(16) __nv_bfloat16 g_Al[(size_t)MTOT * DDIM];   // MLP A lo
// W1 B-fragment table: [nc=4][ks=8][nt=16][lane=32] uint4 = {b0h,b1h,b0l,b1l}
__device__ __align__(16) uint4 g_B1f[4 * 8 * 16 * 32];
// W2 B-fragment table: [kb=32][ntile=3][lane=32]
__device__ __align__(16) uint4 g_W2f[32 * 3 * 32];
// tan combined-weight B-fragment table: [ks=6][t=16][lane=32]
__device__ __align__(16) uint4 g_Gf[6 * 16 * 32];

// ---------------- mma.sync / ldmatrix helpers ----------------
static __device__ __forceinline__ uint32_t smem_to_u32(const void* p) {
    uint32_t a;
    asm("{ .reg .u64 t; cvta.to.shared.u64 t, %1; cvt.u32.u64 %0, t; }"
        : "=r"(a) : "l"(p));
    return a;
}
static __device__ __forceinline__ void ldsm4(uint32_t r[4], uint32_t addr) {
    asm volatile("ldmatrix.sync.aligned.m8n8.x4.shared.b16 {%0,%1,%2,%3}, [%4];"
                 : "=r"(r[0]), "=r"(r[1]), "=r"(r[2]), "=r"(r[3]) : "r"(addr));
}
static __device__ __forceinline__ void ldsm4t(uint32_t r[4], uint32_t addr) {
    asm volatile("ldmatrix.sync.aligned.m8n8.x4.trans.shared.b16 {%0,%1,%2,%3}, [%4];"
                 : "=r"(r[0]), "=r"(r[1]), "=r"(r[2]), "=r"(r[3]) : "r"(addr));
}
static __device__ __forceinline__ void mma_bf16(float d[4], const uint32_t a[4],
                                                uint32_t b0, uint32_t b1) {
    asm volatile(
        "mma.sync.aligned.m16n8k16.row.col.f32.bf16.bf16.f32 "
        "{%0,%1,%2,%3}, {%4,%5,%6,%7}, {%8,%9}, {%0,%1,%2,%3};"
        : "+f"(d[0]), "+f"(d[1]), "+f"(d[2]), "+f"(d[3])
        : "r"(a[0]), "r"(a[1]), "r"(a[2]), "r"(a[3]), "r"(b0), "r"(b1));
}
static __device__ __forceinline__ uint32_t bits2(__nv_bfloat162 v) {
    return *reinterpret_cast<uint32_t*>(&v);
}

// ---------------- warp math helpers ----------------
static __device__ __forceinline__ float wred(float v) {
#pragma unroll
    for (int o = 16; o > 0; o >>= 1) v += __shfl_xor_sync(0xffffffffu, v, o);
    return v;
}

struct F4 { float x, y, z, w; };

static __device__ __forceinline__ float dotred(const F4 &a, const F4 &b) {
    return wred(a.x*b.x + a.y*b.y + a.z*b.z + a.w*b.w);
}

static __device__ __forceinline__ F4 logmap_f(const F4 &x, float sqx,
                                              const F4 &y, float sqy) {
    float xy  = dotred(x, y);
    float txy = -2.0f * xy;
    float cx  = 1.0f + txy + sqy;
    float cy  = 1.0f - sqx;
    float den = fmaxf(1.0f + txy + sqx*sqy, EPSC);
    float inv = 1.0f / den;
    F4 d;
    d.x = (cy*y.x - cx*x.x) * inv;
    d.y = (cy*y.y - cx*x.y) * inv;
    d.z = (cy*y.z - cx*x.z) * inv;
    d.w = (cy*y.w - cx*x.w) * inv;
    float sqd = dotred(d, d);
    float nd  = sqrtf(fmaxf(sqd, EPS2));
    float s   = fmaxf(cy, EPSC) * atanhf(fminf(nd, CLIPC)) / nd;
    F4 r = { d.x*s, d.y*s, d.z*s, d.w*s };
    return r;
}

static __device__ __forceinline__ void expmap_f(const F4 &x, float sqx, const F4 &v,
                                                F4 &zout, float &sqout) {
    float m   = fmaxf(1.0f - sqx, EPSC);
    float sqv = dotred(v, v);
    float nv  = sqrtf(fmaxf(sqv, EPS2));
    float th  = tanhf(nv / m);
    float sc  = th / nv;
    F4 sec = { v.x*sc, v.y*sc, v.z*sc, v.w*sc };
    float xy = dotred(x, sec);
    float y2 = dotred(sec, sec);
    float ca  = 1.0f + 2.0f*xy + y2;
    float cb  = 1.0f - sqx;
    float den = fmaxf(1.0f + 2.0f*xy + sqx*y2, EPSC);
    float inv = 1.0f / den;
    F4 r = { (ca*x.x + cb*sec.x)*inv, (ca*x.y + cb*sec.y)*inv,
             (ca*x.z + cb*sec.z)*inv, (ca*x.w + cb*sec.w)*inv };
    float sqr = dotred(r, r);
    float nr  = sqrtf(fmaxf(sqr, EPS2));
    if (nr > MAXNC) {
        float s = MAXNC / nr;
        r.x *= s; r.y *= s; r.z *= s; r.w *= s;
        sqr *= s * s;
    }
    zout = r; sqout = sqr;
}

// ---------------- hi/lo split of 4 floats into two bf16x2 pairs ------------
static __device__ __forceinline__ void split4(float v0, float v1, float v2, float v3,
                                              uint32_t &h0, uint32_t &h1,
                                              uint32_t &l0, uint32_t &l1) {
    __nv_bfloat162 a = __floats2bfloat162_rn(v0, v1);
    __nv_bfloat162 b = __floats2bfloat162_rn(v2, v3);
    float e0 = v0 - __bfloat162float(__low2bfloat16(a));
    float e1 = v1 - __bfloat162float(__high2bfloat16(a));
    float e2 = v2 - __bfloat162float(__low2bfloat16(b));
    float e3 = v3 - __bfloat162float(__high2bfloat16(b));
    __nv_bfloat162 c = __floats2bfloat162_rn(e0, e1);
    __nv_bfloat162 d = __floats2bfloat162_rn(e2, e3);
    h0 = bits2(a); h1 = bits2(b); l0 = bits2(c); l1 = bits2(d);
}

// ============================================================================
// Merged prep kernel.
// ============================================================================
__global__ void prep_kernel(const float* __restrict__ W1, const float* __restrict__ W2,
                            const float* __restrict__ W_t, const float* __restrict__ W_c,
                            const float* __restrict__ W_f, const float* __restrict__ W_r)
{
    int idx = blockIdx.x * 256 + threadIdx.x;
    if (idx < 16384) {
        int lane = idx & 31;
        int nt   = (idx >> 5) & 15;
        int ks   = (idx >> 9) & 7;
        int nc   = idx >> 12;
        int n    = nc * 128 + nt * 8 + (lane >> 2);
        int k0   = ks * 16 + 2 * (lane & 3);
        float w00 = __ldg(&W1[(size_t)(k0    ) * HDIM + n]);
        float w01 = __ldg(&W1[(size_t)(k0 + 1) * HDIM + n]);
        float w08 = __ldg(&W1[(size_t)(k0 + 8) * HDIM + n]);
        float w09 = __ldg(&W1[(size_t)(k0 + 9) * HDIM + n]);
        uint4 v;
        split4(w00, w01, w08, w09, v.x, v.y, v.z, v.w);
        g_B1f[idx] = v;
    } else if (idx < 16384 + 3072) {
        int e = idx - 16384;
        int lane = e & 31;
        int t    = (e >> 5) % 3;
        int kb   = e / 96;
        int k0   = kb * 16 + 2 * (lane & 3);
        int n    = t * 8 + (lane >> 2);
        float w00 = __ldg(&W2[(size_t)(k0    ) * 24 + n]);
        float w01 = __ldg(&W2[(size_t)(k0 + 1) * 24 + n]);
        float w08 = __ldg(&W2[(size_t)(k0 + 8) * 24 + n]);
        float w09 = __ldg(&W2[(size_t)(k0 + 9) * 24 + n]);
        uint4 v;
        split4(w00, w01, w08, w09, v.x, v.y, v.z, v.w);
        g_W2f[(kb * 3 + t) * 32 + lane] = v;
    } else if (idx < 19456 + 3072) {
        int e = idx - 19456;
        int lane = e & 31;
        int t    = (e >> 5) & 15;
        int ks   = e >> 9;            // 0..5
        int d    = t * 8 + (lane >> 2);
        int k0   = ks * 16 + 2 * (lane & 3);
        float vv[4];
        int kk[4] = { k0, k0 + 1, k0 + 8, k0 + 9 };
#pragma unroll
        for (int q = 0; q < 4; ++q) {
            int k = kk[q];
            int st = k / 24, s = k - st * 24;
            const float* W = (st == 0 ? W_t : st == 1 ? W_c :
                              st == 2 ? W_f : W_r);
            vv[q] = __ldg(&W[s * DDIM + d]);
        }
        uint4 v;
        split4(vv[0], vv[1], vv[2], vv[3], v.x, v.y, v.z, v.w);
        g_Gf[(ks * 16 + t) * 32 + lane] = v;
    }
}

// ============================================================================
// Kernel 1a: tan GEMM on tensor cores + fused expmap0 -> g_z (+ norms g_zn).
// ============================================================================
#define SM2_AH   0
#define SM2_AL   26112
#define SM2_P    52224
#define SM2_BIAS 53248
#define GEMV_SMEM (53248 + 512)       // 53760 B

__global__ void __launch_bounds__(256, 2)
gemv_mma_kernel(const float* __restrict__ trend,  const float* __restrict__ scoarse,
                const float* __restrict__ sfine,  const float* __restrict__ resid,
                const float* __restrict__ b_t, const float* __restrict__ b_c,
                const float* __restrict__ b_f, const float* __restrict__ b_r)
{
    extern __shared__ char smem[];
    const uint32_t sbase = smem_to_u32(smem);
    const int tid  = threadIdx.x;
    const int lane = tid & 31;
    const int wid  = tid >> 5;
    const int mg   = wid >> 1;
    const int ng   = wid & 1;
    const int b    = blockIdx.x / 15;
    const int slot = blockIdx.x - b * 15;

    float* sPart = reinterpret_cast<float*>(smem + SM2_P);
    float* sBias = reinterpret_cast<float*>(smem + SM2_BIAS);

    if (tid < 128)
        sBias[tid] = __ldg(&b_t[tid]) + __ldg(&b_c[tid]) +
                     __ldg(&b_f[tid]) + __ldg(&b_r[tid]);

    // ---- stage A^T hi/lo ----
    const size_t base_b = (size_t)b * LTOT * FEAT;
#pragma unroll
    for (int it = 0; it < 12; ++it) {
        int i  = tid + it * 256;
        int k  = i >> 5;
        int c4 = i & 31;
        int st = k / 24, s = k - st * 24;
        const float* src = (st == 0 ? trend : st == 1 ? scoarse :
                            st == 2 ? sfine : resid);
        float4 v = __ldg(reinterpret_cast<const float4*>(
            &src[base_b + (size_t)(360 + slot * 24 + s) * FEAT]) + c4);
        uint32_t h0, h1, l0, l1;
        split4(v.x, v.y, v.z, v.w, h0, h1, l0, l1);
        uint32_t off = (uint32_t)(k * 136 + c4 * 4) * 2;
        *reinterpret_cast<uint2*>(smem + SM2_AH + off) = make_uint2(h0, h1);
        *reinterpret_cast<uint2*>(smem + SM2_AL + off) = make_uint2(l0, l1);
    }
    __syncthreads();

    uint32_t aoffh[2], aoffl[2];
    {
        int kRow = (lane & 7) + ((lane >> 4) << 3);
        int mC8  = ((lane >> 3) & 1) << 3;
#pragma unroll
        for (int mt = 0; mt < 2; ++mt) {
            uint32_t off = (uint32_t)(kRow * 136 + mg * 32 + mt * 16 + mC8) * 2;
            aoffh[mt] = sbase + SM2_AH + off;
            aoffl[mt] = sbase + SM2_AL + off;
        }
    }

    float acc[2][8][4];
#pragma unroll
    for (int mt = 0; mt < 2; ++mt)
#pragma unroll
        for (int nt = 0; nt < 8; ++nt)
#pragma unroll
            for (int q = 0; q < 4; ++q) acc[mt][nt][q] = 0.0f;

#pragma unroll
    for (int ks = 0; ks < 6; ++ks) {
        uint32_t ah[2][4], al[2][4];
        ldsm4t(ah[0], aoffh[0] + ks * 16 * 272);
        ldsm4t(ah[1], aoffh[1] + ks * 16 * 272);
        ldsm4t(al[0], aoffl[0] + ks * 16 * 272);
        ldsm4t(al[1], aoffl[1] + ks * 16 * 272);
#pragma unroll
        for (int g4 = 0; g4 < 4; ++g4) {
            const int t0 = ng * 8 + 2 * g4;
            uint4 e0 = __ldg(&g_Gf[(ks * 16 + t0) * 32 + lane]);
            uint4 e1 = __ldg(&g_Gf[(ks * 16 + t0 + 1) * 32 + lane]);
#pragma unroll
            for (int mt = 0; mt < 2; ++mt) {
                mma_bf16(acc[mt][2*g4],   ah[mt], e0.x, e0.y);
                mma_bf16(acc[mt][2*g4+1], ah[mt], e1.x, e1.y);
                mma_bf16(acc[mt][2*g4],   al[mt], e0.x, e0.y);
                mma_bf16(acc[mt][2*g4+1], al[mt], e1.x, e1.y);
                mma_bf16(acc[mt][2*g4],   ah[mt], e0.z, e0.w);
                mma_bf16(acc[mt][2*g4+1], ah[mt], e1.z, e1.w);
            }
        }
    }

    float p[2][2];
#pragma unroll
    for (int mt = 0; mt < 2; ++mt) { p[mt][0] = 0.0f; p[mt][1] = 0.0f; }
#pragma unroll
    for (int nt = 0; nt < 8; ++nt) {
        int c = ng * 64 + nt * 8 + 2 * (lane & 3);
        float bx = sBias[c], by = sBias[c + 1];
#pragma unroll
        for (int mt = 0; mt < 2; ++mt) {
            acc[mt][nt][0] += bx; acc[mt][nt][1] += by;
            acc[mt][nt][2] += bx; acc[mt][nt][3] += by;
            p[mt][0] += acc[mt][nt][0]*acc[mt][nt][0] + acc[mt][nt][1]*acc[mt][nt][1];
            p[mt][1] += acc[mt][nt][2]*acc[mt][nt][2] + acc[mt][nt][3]*acc[mt][nt][3];
        }
    }
#pragma unroll
    for (int mt = 0; mt < 2; ++mt) {
#pragma unroll
        for (int h = 0; h < 2; ++h) {
            p[mt][h] += __shfl_xor_sync(0xffffffffu, p[mt][h], 1);
            p[mt][h] += __shfl_xor_sync(0xffffffffu, p[mt][h], 2);
        }
        if ((lane & 3) == 0) {
            int r0 = mg * 32 + mt * 16 + (lane >> 2);
            sPart[r0 * 2 + ng]       = p[mt][0];
            sPart[(r0 + 8) * 2 + ng] = p[mt][1];
        }
    }
    __syncthreads();

    float* gz = &g_z[((size_t)slot * NROWS + (size_t)b * 128) * DDIM];
    float* gn = &g_zn[(size_t)slot * NROWS + (size_t)b * 128];
#pragma unroll
    for (int mt = 0; mt < 2; ++mt) {
        int r0 = mg * 32 + mt * 16 + (lane >> 2);
        float sq0 = sPart[r0 * 2] + sPart[r0 * 2 + 1];
        float sq1 = sPart[(r0 + 8) * 2] + sPart[(r0 + 8) * 2 + 1];
        float n0 = sqrtf(fmaxf(sq0, EPS2));
        float n1 = sqrtf(fmaxf(sq1, EPS2));
        float t0 = tanhf(n0), t1 = tanhf(n1);
        float sc0 = (t0 > MAXNC ? MAXNC : t0) / n0;
        float sc1 = (t1 > MAXNC ? MAXNC : t1) / n1;
        if (ng == 0 && (lane & 3) == 0) {
            gn[r0]     = sq0 * sc0 * sc0;
            gn[r0 + 8] = sq1 * sc1 * sc1;
        }
#pragma unroll
        for (int nt = 0; nt < 8; ++nt) {
            int c = ng * 64 + nt * 8 + 2 * (lane & 3);
            *reinterpret_cast<float2*>(&gz[r0 * 128 + c]) =
                make_float2(acc[mt][nt][0] * sc0, acc[mt][nt][1] * sc0);
            *reinterpret_cast<float2*>(&gz[(r0 + 8) * 128 + c]) =
                make_float2(acc[mt][nt][2] * sc1, acc[mt][nt][3] * sc1);
        }
    }
}

// ============================================================================
// Kernel 1b: hyperbolic chain (uses precomputed norms g_zn)
// ============================================================================
static __device__ __forceinline__ F4 ldz(int slot, int row, int lane) {
    float4 v = __ldg(reinterpret_cast<const float4*>(
        &g_z[((size_t)slot * NROWS + row) * DDIM + lane * 4]));
    F4 r = { v.x, v.y, v.z, v.w };
    return r;
}
static __device__ __forceinline__ float ldn(int slot, int row) {
    return __ldg(&g_zn[(size_t)slot * NROWS + row]);
}

__global__ void __launch_bounds__(256, 3)
chain_kernel(const float* __restrict__ alpha_p)
{
    const int tid  = threadIdx.x;
    const int wid  = tid >> 5;
    const int lane = tid & 31;
    const int row  = blockIdx.x * 8 + wid;

    float s = 0.0f, wv = 1.0f;
#pragma unroll
    for (int j = 13; j >= 0; --j) { s += wv; if (j > 0) wv *= DECAYF; }
    const float w0  = wv / s;
    const float w13 = 1.0f / s;
    const float invd = 1.0f / DECAYF;

    F4 za = ldz(0, row, lane);
    F4 zb = ldz(1, row, lane);
    F4 zc = ldz(2, row, lane);
    float sqa = ldn(0, row);
    float sqb = ldn(1, row);
    float sqc = ldn(2, row);

    F4 avg = {0,0,0,0};
    F4 vel0, vel1, vel2;
    float wj = w0;

#pragma unroll
    for (int j = 0; j < 14; ++j) {
        F4 vel = logmap_f(za, sqa, zb, sqb);
        avg.x += wj * vel.x; avg.y += wj * vel.y;
        avg.z += wj * vel.z; avg.w += wj * vel.w;
        if (j == 0) vel0 = vel;
        else if (j == 1) vel1 = vel;
        else if (j == 2) vel2 = vel;
        wj *= invd;
        za = zb; sqa = sqb;
        zb = zc; sqb = sqc;
        if (j + 3 < WINN) { zc = ldz(j + 3, row, lane); sqc = ldn(j + 3, row); }
    }

    const float alpha = __ldg(alpha_p);
    F4 zl = za; float sql = sqa;
#pragma unroll
    for (int k = 0; k < NPREDK; ++k) {
        F4 v = { avg.x * alpha, avg.y * alpha, avg.z * alpha, avg.w * alpha };
        F4 zn; float sqn;
        expmap_f(zl, sql, v, zn, sqn);

        float n  = sqrtf(fmaxf(sqn, EPS2));
        float sc = atanhf(fminf(n, CLIPC)) / n;
        const size_t m = (size_t)k * NROWS + row;
        uint32_t h0, h1, l0, l1;
        split4(zn.x * sc, zn.y * sc, zn.z * sc, zn.w * sc, h0, h1, l0, l1);
        size_t off = m * DDIM + lane * 4;
        *reinterpret_cast<uint2*>(g_Ah + off) = make_uint2(h0, h1);
        *reinterpret_cast<uint2*>(g_Al + off) = make_uint2(l0, l1);

        if (k < 3) {
            F4 vn = logmap_f(zl, sql, zn, sqn);
            F4 vk = (k == 0 ? vel0 : (k == 1 ? vel1 : vel2));
            avg.x = (avg.x - w0 * vk.x) * DECAYF + w13 * vn.x;
            avg.y = (avg.y - w0 * vk.y) * DECAYF + w13 * vn.y;
            avg.z = (avg.z - w0 * vk.z) * DECAYF + w13 * vn.z;
            avg.w = (avg.w - w0 * vk.w) * DECAYF + w13 * vn.w;
        }
        zl = zn; sql = sqn;
    }
}

// ============================================================================
// Kernel 2: MLP fully on tensor cores, N processed in 32-col halves so the
// live accumulator set is 16 regs -> 3 CTAs/SM (24 warps).
// ============================================================================
#define SM_AH 0
#define SM_AL 16384
#define MLP_SMEM 32768

__global__ void __launch_bounds__(256, 3)
mlp_mma_kernel(const float* __restrict__ b1, const float* __restrict__ b2,
               float* __restrict__ out)
{
    extern __shared__ char smem[];
    const uint32_t sbase = smem_to_u32(smem);
    const int tid  = threadIdx.x;
    const int lane = tid & 31;
    const int wid  = tid >> 5;
    const int mg   = wid >> 1;          // 0..3 : rows mg*16
    const int ng   = wid & 1;           // 0..1 : hidden cols ng*64
    const int m0   = blockIdx.x * 64;

    // ---- stage A hi/lo (apply swizzle) ----
    {
        const uint4* gah = reinterpret_cast<const uint4*>(&g_Ah[(size_t)m0 * DDIM]);
        const uint4* gal = reinterpret_cast<const uint4*>(&g_Al[(size_t)m0 * DDIM]);
#pragma unroll
        for (int i = tid; i < 1024; i += 256) {
            int r = i >> 4, kc = i & 15;
            uint32_t off = (uint32_t)(r * 256 + ((kc * 16) ^ ((r & 7) << 4)));
            *reinterpret_cast<uint4*>(smem + SM_AH + off) = __ldg(gah + i);
            *reinterpret_cast<uint4*>(smem + SM_AL + off) = __ldg(gal + i);
        }
    }
    __syncthreads();

    // ---- A fragment addresses (XOR-swizzled) ----
    const int rA = mg * 16 + (lane & 15);
    const uint32_t tmask_a = (uint32_t)((((lane >> 4) << 4)) ^ ((rA & 7) << 4));
    const uint32_t abase_h = sbase + SM_AH + rA * 256;
    const uint32_t abase_l = sbase + SM_AL + rA * 256;

    float cacc[3][4];
#pragma unroll
    for (int t = 0; t < 3; ++t)
#pragma unroll
        for (int q = 0; q < 4; ++q) cacc[t][q] = 0.0f;

#pragma unroll
    for (int nc = 0; nc < 4; ++nc) {
#pragma unroll
        for (int h = 0; h < 2; ++h) {
            float acc[4][4];
#pragma unroll
            for (int nt = 0; nt < 4; ++nt)
#pragma unroll
                for (int q = 0; q < 4; ++q) acc[nt][q] = 0.0f;

            // ---- GEMM1 mma loop: 32 cols, B frags straight from table ----
            const uint4* btab =
                &g_B1f[(((size_t)nc * 8) * 16 + ng * 8 + h * 4) * 32 + lane];
#pragma unroll
            for (int ks = 0; ks < 8; ++ks) {
                const uint32_t xo = (uint32_t)(ks * 32);
                uint32_t ah[4], al[4];
                ldsm4(ah, abase_h + (xo ^ tmask_a));
                ldsm4(al, abase_l + (xo ^ tmask_a));
                const uint4* bk = btab + (size_t)ks * 16 * 32;
#pragma unroll
                for (int nt = 0; nt < 4; ++nt) {
                    uint4 e = __ldg(bk + nt * 32);
                    mma_bf16(acc[nt], ah, e.x, e.y);
                    mma_bf16(acc[nt], al, e.x, e.y);
                    mma_bf16(acc[nt], ah, e.z, e.w);
                }
            }

            // ---- epilogue: bias+relu -> bf16 A-frags -> GEMM2 relay ----
            const int kb0 = nc * 8 + ng * 4 + h * 2;
#pragma unroll
            for (int ks2 = 0; ks2 < 2; ++ks2) {
                uint32_t ah[4], al[4];
#pragma unroll
                for (int half = 0; half < 2; ++half) {
                    int nt = 2 * ks2 + half;
                    int cB = ng * 64 + h * 32 + nt * 8 + 2 * (lane & 3);
                    float2 b1v = __ldg(reinterpret_cast<const float2*>(
                        &b1[nc * 128 + cB]));
                    float h0 = fmaxf(acc[nt][0] + b1v.x, 0.0f);
                    float h1 = fmaxf(acc[nt][1] + b1v.y, 0.0f);
                    float h2 = fmaxf(acc[nt][2] + b1v.x, 0.0f);
                    float h3 = fmaxf(acc[nt][3] + b1v.y, 0.0f);
                    uint32_t p0, p1, q0, q1;
                    split4(h0, h1, h2, h3, p0, p1, q0, q1);
                    ah[2*half]     = p0;
                    ah[2*half + 1] = p1;
                    al[2*half]     = q0;
                    al[2*half + 1] = q1;
                }
#pragma unroll
                for (int t = 0; t < 3; ++t) {
                    uint4 bw = __ldg(&g_W2f[((kb0 + ks2) * 3 + t) * 32 + lane]);
                    mma_bf16(cacc[t], ah, bw.x, bw.y);
                    mma_bf16(cacc[t], al, bw.x, bw.y);
                    mma_bf16(cacc[t], ah, bw.z, bw.w);
                }
            }
        }
    }

    // ---- cross-ng reduction (smem, reuse A region) + output write ----
    __syncthreads();
    float* P1 = reinterpret_cast<float*>(smem);            // [64][26]
    float* Rb = reinterpret_cast<float*>(smem + 8192);     // [64][26]
    const int r0 = mg * 16 + (lane >> 2);
    if (ng == 1) {
#pragma unroll
        for (int t = 0; t < 3; ++t) {
            int j0 = t * 8 + 2 * (lane & 3);
            P1[r0 * 26 + j0]           = cacc[t][0];
            P1[r0 * 26 + j0 + 1]       = cacc[t][1];
            P1[(r0 + 8) * 26 + j0]     = cacc[t][2];
            P1[(r0 + 8) * 26 + j0 + 1] = cacc[t][3];
        }
    }
    __syncthreads();
    if (ng == 0) {
#pragma unroll
        for (int t = 0; t < 3; ++t) {
            int j0 = t * 8 + 2 * (lane & 3);
            Rb[r0 * 26 + j0]           = cacc[t][0] + P1[r0 * 26 + j0];
            Rb[r0 * 26 + j0 + 1]       = cacc[t][1] + P1[r0 * 26 + j0 + 1];
            Rb[(r0 + 8) * 26 + j0]     = cacc[t][2] + P1[(r0 + 8) * 26 + j0];
            Rb[(r0 + 8) * 26 + j0 + 1] = cacc[t][3] + P1[(r0 + 8) * 26 + j0 + 1];
        }
    }
    __syncthreads();

    {
        const int kidx = m0 >> 14;
        const int bf0  = m0 & 16383;
        const int bb   = bf0 >> 7;
        const int f0   = bf0 & 127;
#pragma unroll
        for (int i = tid; i < 1536; i += 256) {
            int j = i >> 6, f = i & 63;
            out[((size_t)bb * 96 + kidx * 24 + j) * 128 + f0 + f] =
                Rb[f * 26 + j] + __ldg(&b2[j]);
        }
    }
}

// ============================================================================
extern "C" void kernel_launch(void* const* d_in, const int* in_sizes, int n_in,
                              void* d_out, int out_size) {
    const float* trend   = (const float*)d_in[0];
    const float* scoarse = (const float*)d_in[1];
    const float* sfine   = (const float*)d_in[2];
    const float* resid   = (const float*)d_in[3];
    const float* W_t = (const float*)d_in[4];
    const float* b_t = (const float*)d_in[5];
    const float* W_c = (const float*)d_in[6];
    const float* b_c = (const float*)d_in[7];
    const float* W_f = (const float*)d_in[8];
    const float* b_f = (const float*)d_in[9];
    const float* W_r = (const float*)d_in[10];
    const float* b_r = (const float*)d_in[11];
    const float* alpha = (const float*)d_in[12];
    const float* W1 = (const float*)d_in[13];
    const float* b1 = (const float*)d_in[14];
    const float* W2 = (const float*)d_in[15];
    const float* b2 = (const float*)d_in[16];

    cudaFuncSetAttribute(mlp_mma_kernel,
                         cudaFuncAttributeMaxDynamicSharedMemorySize, MLP_SMEM);
    cudaFuncSetAttribute(gemv_mma_kernel,
                         cudaFuncAttributeMaxDynamicSharedMemorySize, GEMV_SMEM);

    prep_kernel<<<88, 256>>>(W1, W2, W_t, W_c, W_f, W_r);
    gemv_mma_kernel<<<1920, 256, GEMV_SMEM>>>(trend, scoarse, sfine, resid,
                                              b_t, b_c, b_f, b_r);
    chain_kernel<<<NROWS / 8, 256>>>(alpha);
    mlp_mma_kernel<<<MTOT / 64, 256, MLP_SMEM>>>(b1, b2, (float*)d_out);
}

// round 14
// speedup vs baseline: 1.4620x; 1.4620x over previous
#include <cuda_runtime.h>
#include <cuda_bf16.h>
#include <cstdint>

#define BATCH   128
#define LTOT    720
#define FEAT    128
#define SEGL    24
#define WINN    15
#define NPREDK  4
#define DDIM    128
#define HDIM    512
#define NROWS   (BATCH*FEAT)
#define MTOT    (NPREDK*NROWS)
#define EPSC    1e-6f
#define EPS2    1e-12f
#define MAXNC   0.99999f
#define CLIPC   0.99999988f
#define DECAYF  0.9f

__device__ float g_z[(size_t)WINN * NROWS * DDIM];
__device__ float g_zn[(size_t)WINN * NROWS];
__device__ __align__(16) __nv_bfloat16 g_Ah[(size_t)MTOT * DDIM];
__device__ __align__(16) __nv_bfloat16 g_Al[(size_t)MTOT * DDIM];
__device__ __align__(16) uint4 g_B1f[4 * 8 * 16 * 32];
__device__ __align__(16) uint4 g_W2f[32 * 3 * 32];
__device__ __align__(16) uint4 g_Gf[6 * 16 * 32];

static __device__ __forceinline__ uint32_t smem_to_u32(const void* p) {
    uint32_t a;
    asm("{ .reg .u64 t; cvta.to.shared.u64 t, %1; cvt.u32.u64 %0, t; }"
        : "=r"(a) : "l"(p));
    return a;
}
static __device__ __forceinline__ void ldsm4(uint32_t r[4], uint32_t addr) {
    asm volatile("ldmatrix.sync.aligned.m8n8.x4.shared.b16 {%0,%1,%2,%3}, [%4];"
                 : "=r"(r[0]), "=r"(r[1]), "=r"(r[2]), "=r"(r[3]) : "r"(addr));
}
static __device__ __forceinline__ void ldsm4t(uint32_t r[4], uint32_t addr) {
    asm volatile("ldmatrix.sync.aligned.m8n8.x4.trans.shared.b16 {%0,%1,%2,%3}, [%4];"
                 : "=r"(r[0]), "=r"(r[1]), "=r"(r[2]), "=r"(r[3]) : "r"(addr));
}
static __device__ __forceinline__ void mma_bf16(float d[4], const uint32_t a[4],
                                                uint32_t b0, uint32_t b1) {
    asm volatile(
        "mma.sync.aligned.m16n8k16.row.col.f32.bf16.bf16.f32 "
        "{%0,%1,%2,%3}, {%4,%5,%6,%7}, {%8,%9}, {%0,%1,%2,%3};"
        : "+f"(d[0]), "+f"(d[1]), "+f"(d[2]), "+f"(d[3])
        : "r"(a[0]), "r"(a[1]), "r"(a[2]), "r"(a[3]), "r"(b0), "r"(b1));
}
static __device__ __forceinline__ uint32_t bits2(__nv_bfloat162 v) {
    return *reinterpret_cast<uint32_t*>(&v);
}

static __device__ __forceinline__ float wred(float v) {
#pragma unroll
    for (int o = 16; o > 0; o >>= 1) v += __shfl_xor_sync(0xffffffffu, v, o);
    return v;
}
static __device__ __forceinline__ void wred2(float &a, float &b) {
#pragma unroll
    for (int o = 16; o > 0; o >>= 1) {
        float ta = __shfl_xor_sync(0xffffffffu, a, o);
        float tb = __shfl_xor_sync(0xffffffffu, b, o);
        a += ta; b += tb;
    }
}

struct F4 { float x, y, z, w; };

static __device__ __forceinline__ float dot4(const F4 &a, const F4 &b) {
    return a.x*b.x + a.y*b.y + a.z*b.z + a.w*b.w;
}

// logmap with SCALAR ||d||^2: one warp reduction (xy) instead of two.
static __device__ __forceinline__ F4 logmap_s(const F4 &x, float sqx,
                                              const F4 &y, float sqy) {
    float xy  = wred(dot4(x, y));
    float txy = -2.0f * xy;
    float cx  = 1.0f + txy + sqy;
    float cy  = 1.0f - sqx;
    float den = fmaxf(1.0f + txy + sqx*sqy, EPSC);
    float inv = 1.0f / den;
    float sqd = inv*inv * (cy*cy*sqy - 2.0f*cy*cx*xy + cx*cx*sqx);
    float nd  = sqrtf(fmaxf(sqd, EPS2));
    float s   = fmaxf(cy, EPSC) * atanhf(fminf(nd, CLIPC)) / nd * inv;
    F4 r = { (cy*y.x - cx*x.x) * s, (cy*y.y - cx*x.y) * s,
             (cy*y.z - cx*x.z) * s, (cy*y.w - cx*x.w) * s };
    return r;
}

// expmap with scalar ||r||^2: two INDEPENDENT (interleaved) reductions.
static __device__ __forceinline__ void expmap_s(const F4 &x, float sqx, const F4 &v,
                                                F4 &zout, float &sqout) {
    float pa = dot4(v, v);
    float pb = dot4(x, v);
    wred2(pa, pb);
    float m   = fmaxf(1.0f - sqx, EPSC);
    float nv  = sqrtf(fmaxf(pa, EPS2));
    float th  = tanhf(nv / m);
    float sc  = th / nv;
    float xy  = sc * pb;
    float y2  = sc * sc * pa;
    float ca  = 1.0f + 2.0f*xy + y2;
    float cb  = 1.0f - sqx;
    float den = fmaxf(1.0f + 2.0f*xy + sqx*y2, EPSC);
    float inv = 1.0f / den;
    float cbs = cb * sc;
    F4 r = { (ca*x.x + cbs*v.x)*inv, (ca*x.y + cbs*v.y)*inv,
             (ca*x.z + cbs*v.z)*inv, (ca*x.w + cbs*v.w)*inv };
    float sqr = inv*inv * (ca*ca*sqx + 2.0f*ca*cb*xy + cb*cb*y2);
    float nr  = sqrtf(fmaxf(sqr, EPS2));
    if (nr > MAXNC) {
        float s = MAXNC / nr;
        r.x *= s; r.y *= s; r.z *= s; r.w *= s;
        sqr *= s * s;
    }
    zout = r; sqout = sqr;
}

static __device__ __forceinline__ void split4(float v0, float v1, float v2, float v3,
                                              uint32_t &h0, uint32_t &h1,
                                              uint32_t &l0, uint32_t &l1) {
    __nv_bfloat162 a = __floats2bfloat162_rn(v0, v1);
    __nv_bfloat162 b = __floats2bfloat162_rn(v2, v3);
    float e0 = v0 - __bfloat162float(__low2bfloat16(a));
    float e1 = v1 - __bfloat162float(__high2bfloat16(a));
    float e2 = v2 - __bfloat162float(__low2bfloat16(b));
    float e3 = v3 - __bfloat162float(__high2bfloat16(b));
    __nv_bfloat162 c = __floats2bfloat162_rn(e0, e1);
    __nv_bfloat162 d = __floats2bfloat162_rn(e2, e3);
    h0 = bits2(a); h1 = bits2(b); l0 = bits2(c); l1 = bits2(d);
}

// ============================================================================
__global__ void prep_kernel(const float* __restrict__ W1, const float* __restrict__ W2,
                            const float* __restrict__ W_t, const float* __restrict__ W_c,
                            const float* __restrict__ W_f, const float* __restrict__ W_r)
{
    int idx = blockIdx.x * 256 + threadIdx.x;
    if (idx < 16384) {
        int lane = idx & 31;
        int nt   = (idx >> 5) & 15;
        int ks   = (idx >> 9) & 7;
        int nc   = idx >> 12;
        int n    = nc * 128 + nt * 8 + (lane >> 2);
        int k0   = ks * 16 + 2 * (lane & 3);
        float w00 = __ldg(&W1[(size_t)(k0    ) * HDIM + n]);
        float w01 = __ldg(&W1[(size_t)(k0 + 1) * HDIM + n]);
        float w08 = __ldg(&W1[(size_t)(k0 + 8) * HDIM + n]);
        float w09 = __ldg(&W1[(size_t)(k0 + 9) * HDIM + n]);
        uint4 v;
        split4(w00, w01, w08, w09, v.x, v.y, v.z, v.w);
        g_B1f[idx] = v;
    } else if (idx < 16384 + 3072) {
        int e = idx - 16384;
        int lane = e & 31;
        int t    = (e >> 5) % 3;
        int kb   = e / 96;
        int k0   = kb * 16 + 2 * (lane & 3);
        int n    = t * 8 + (lane >> 2);
        float w00 = __ldg(&W2[(size_t)(k0    ) * 24 + n]);
        float w01 = __ldg(&W2[(size_t)(k0 + 1) * 24 + n]);
        float w08 = __ldg(&W2[(size_t)(k0 + 8) * 24 + n]);
        float w09 = __ldg(&W2[(size_t)(k0 + 9) * 24 + n]);
        uint4 v;
        split4(w00, w01, w08, w09, v.x, v.y, v.z, v.w);
        g_W2f[(kb * 3 + t) * 32 + lane] = v;
    } else if (idx < 19456 + 3072) {
        int e = idx - 19456;
        int lane = e & 31;
        int t    = (e >> 5) & 15;
        int ks   = e >> 9;
        int d    = t * 8 + (lane >> 2);
        int k0   = ks * 16 + 2 * (lane & 3);
        float vv[4];
        int kk[4] = { k0, k0 + 1, k0 + 8, k0 + 9 };
#pragma unroll
        for (int q = 0; q < 4; ++q) {
            int k = kk[q];
            int st = k / 24, s = k - st * 24;
            const float* W = (st == 0 ? W_t : st == 1 ? W_c :
                              st == 2 ? W_f : W_r);
            vv[q] = __ldg(&W[s * DDIM + d]);
        }
        uint4 v;
        split4(vv[0], vv[1], vv[2], vv[3], v.x, v.y, v.z, v.w);
        g_Gf[(ks * 16 + t) * 32 + lane] = v;
    }
}

// ============================================================================
#define SM2_AH   0
#define SM2_AL   26112
#define SM2_P    52224
#define SM2_BIAS 53248
#define GEMV_SMEM (53248 + 512)

__global__ void __launch_bounds__(256, 2)
gemv_mma_kernel(const float* __restrict__ trend,  const float* __restrict__ scoarse,
                const float* __restrict__ sfine,  const float* __restrict__ resid,
                const float* __restrict__ b_t, const float* __restrict__ b_c,
                const float* __restrict__ b_f, const float* __restrict__ b_r)
{
    extern __shared__ char smem[];
    const uint32_t sbase = smem_to_u32(smem);
    const int tid  = threadIdx.x;
    const int lane = tid & 31;
    const int wid  = tid >> 5;
    const int mg   = wid >> 1;
    const int ng   = wid & 1;
    const int b    = blockIdx.x / 15;
    const int slot = blockIdx.x - b * 15;

    float* sPart = reinterpret_cast<float*>(smem + SM2_P);
    float* sBias = reinterpret_cast<float*>(smem + SM2_BIAS);

    if (tid < 128)
        sBias[tid] = __ldg(&b_t[tid]) + __ldg(&b_c[tid]) +
                     __ldg(&b_f[tid]) + __ldg(&b_r[tid]);

    const size_t base_b = (size_t)b * LTOT * FEAT;
#pragma unroll
    for (int it = 0; it < 12; ++it) {
        int i  = tid + it * 256;
        int k  = i >> 5;
        int c4 = i & 31;
        int st = k / 24, s = k - st * 24;
        const float* src = (st == 0 ? trend : st == 1 ? scoarse :
                            st == 2 ? sfine : resid);
        float4 v = __ldg(reinterpret_cast<const float4*>(
            &src[base_b + (size_t)(360 + slot * 24 + s) * FEAT]) + c4);
        uint32_t h0, h1, l0, l1;
        split4(v.x, v.y, v.z, v.w, h0, h1, l0, l1);
        uint32_t off = (uint32_t)(k * 136 + c4 * 4) * 2;
        *reinterpret_cast<uint2*>(smem + SM2_AH + off) = make_uint2(h0, h1);
        *reinterpret_cast<uint2*>(smem + SM2_AL + off) = make_uint2(l0, l1);
    }
    __syncthreads();

    uint32_t aoffh[2], aoffl[2];
    {
        int kRow = (lane & 7) + ((lane >> 4) << 3);
        int mC8  = ((lane >> 3) & 1) << 3;
#pragma unroll
        for (int mt = 0; mt < 2; ++mt) {
            uint32_t off = (uint32_t)(kRow * 136 + mg * 32 + mt * 16 + mC8) * 2;
            aoffh[mt] = sbase + SM2_AH + off;
            aoffl[mt] = sbase + SM2_AL + off;
        }
    }

    float acc[2][8][4];
#pragma unroll
    for (int mt = 0; mt < 2; ++mt)
#pragma unroll
        for (int nt = 0; nt < 8; ++nt)
#pragma unroll
            for (int q = 0; q < 4; ++q) acc[mt][nt][q] = 0.0f;

#pragma unroll
    for (int ks = 0; ks < 6; ++ks) {
        uint32_t ah[2][4], al[2][4];
        ldsm4t(ah[0], aoffh[0] + ks * 16 * 272);
        ldsm4t(ah[1], aoffh[1] + ks * 16 * 272);
        ldsm4t(al[0], aoffl[0] + ks * 16 * 272);
        ldsm4t(al[1], aoffl[1] + ks * 16 * 272);
#pragma unroll
        for (int g4 = 0; g4 < 4; ++g4) {
            const int t0 = ng * 8 + 2 * g4;
            uint4 e0 = __ldg(&g_Gf[(ks * 16 + t0) * 32 + lane]);
            uint4 e1 = __ldg(&g_Gf[(ks * 16 + t0 + 1) * 32 + lane]);
#pragma unroll
            for (int mt = 0; mt < 2; ++mt) {
                mma_bf16(acc[mt][2*g4],   ah[mt], e0.x, e0.y);
                mma_bf16(acc[mt][2*g4+1], ah[mt], e1.x, e1.y);
                mma_bf16(acc[mt][2*g4],   al[mt], e0.x, e0.y);
                mma_bf16(acc[mt][2*g4+1], al[mt], e1.x, e1.y);
                mma_bf16(acc[mt][2*g4],   ah[mt], e0.z, e0.w);
                mma_bf16(acc[mt][2*g4+1], ah[mt], e1.z, e1.w);
            }
        }
    }

    float p[2][2];
#pragma unroll
    for (int mt = 0; mt < 2; ++mt) { p[mt][0] = 0.0f; p[mt][1] = 0.0f; }
#pragma unroll
    for (int nt = 0; nt < 8; ++nt) {
        int c = ng * 64 + nt * 8 + 2 * (lane & 3);
        float bx = sBias[c], by = sBias[c + 1];
#pragma unroll
        for (int mt = 0; mt < 2; ++mt) {
            acc[mt][nt][0] += bx; acc[mt][nt][1] += by;
            acc[mt][nt][2] += bx; acc[mt][nt][3] += by;
            p[mt][0] += acc[mt][nt][0]*acc[mt][nt][0] + acc[mt][nt][1]*acc[mt][nt][1];
            p[mt][1] += acc[mt][nt][2]*acc[mt][nt][2] + acc[mt][nt][3]*acc[mt][nt][3];
        }
    }
#pragma unroll
    for (int mt = 0; mt < 2; ++mt) {
#pragma unroll
        for (int h = 0; h < 2; ++h) {   // quad-local reduction ONLY
            p[mt][h] += __shfl_xor_sync(0xffffffffu, p[mt][h], 1);
            p[mt][h] += __shfl_xor_sync(0xffffffffu, p[mt][h], 2);
        }
        if ((lane & 3) == 0) {
            int r0 = mg * 32 + mt * 16 + (lane >> 2);
            sPart[r0 * 2 + ng]       = p[mt][0];
            sPart[(r0 + 8) * 2 + ng] = p[mt][1];
        }
    }
    __syncthreads();

    float* gz = &g_z[((size_t)slot * NROWS + (size_t)b * 128) * DDIM];
    float* gn = &g_zn[(size_t)slot * NROWS + (size_t)b * 128];
#pragma unroll
    for (int mt = 0; mt < 2; ++mt) {
        int r0 = mg * 32 + mt * 16 + (lane >> 2);
        float sq0 = sPart[r0 * 2] + sPart[r0 * 2 + 1];
        float sq1 = sPart[(r0 + 8) * 2] + sPart[(r0 + 8) * 2 + 1];
        float n0 = sqrtf(fmaxf(sq0, EPS2));
        float n1 = sqrtf(fmaxf(sq1, EPS2));
        float t0 = tanhf(n0), t1 = tanhf(n1);
        float sc0 = (t0 > MAXNC ? MAXNC : t0) / n0;
        float sc1 = (t1 > MAXNC ? MAXNC : t1) / n1;
        if (ng == 0 && (lane & 3) == 0) {
            gn[r0]     = sq0 * sc0 * sc0;
            gn[r0 + 8] = sq1 * sc1 * sc1;
        }
#pragma unroll
        for (int nt = 0; nt < 8; ++nt) {
            int c = ng * 64 + nt * 8 + 2 * (lane & 3);
            *reinterpret_cast<float2*>(&gz[r0 * 128 + c]) =
                make_float2(acc[mt][nt][0] * sc0, acc[mt][nt][1] * sc0);
            *reinterpret_cast<float2*>(&gz[(r0 + 8) * 128 + c]) =
                make_float2(acc[mt][nt][2] * sc1, acc[mt][nt][3] * sc1);
        }
    }
}

// ============================================================================
static __device__ __forceinline__ F4 ldz(int slot, int row, int lane) {
    float4 v = __ldg(reinterpret_cast<const float4*>(
        &g_z[((size_t)slot * NROWS + row) * DDIM + lane * 4]));
    F4 r = { v.x, v.y, v.z, v.w };
    return r;
}
static __device__ __forceinline__ float ldn(int slot, int row) {
    return __ldg(&g_zn[(size_t)slot * NROWS + row]);
}

__global__ void __launch_bounds__(256, 3)
chain_kernel(const float* __restrict__ alpha_p)
{
    const int tid  = threadIdx.x;
    const int wid  = tid >> 5;
    const int lane = tid & 31;
    const int row  = blockIdx.x * 8 + wid;

    float s = 0.0f, wv = 1.0f;
#pragma unroll
    for (int j = 13; j >= 0; --j) { s += wv; if (j > 0) wv *= DECAYF; }
    const float w0  = wv / s;
    const float w13 = 1.0f / s;
    const float invd = 1.0f / DECAYF;

    F4 za = ldz(0, row, lane);
    F4 zb = ldz(1, row, lane);
    F4 zc = ldz(2, row, lane);
    float sqa = ldn(0, row);
    float sqb = ldn(1, row);
    float sqc = ldn(2, row);

    F4 avg = {0,0,0,0};
    F4 vel0, vel1, vel2;
    float wj = w0;

#pragma unroll
    for (int j = 0; j < 14; ++j) {
        F4 vel = logmap_s(za, sqa, zb, sqb);
        avg.x += wj * vel.x; avg.y += wj * vel.y;
        avg.z += wj * vel.z; avg.w += wj * vel.w;
        if (j == 0) vel0 = vel;
        else if (j == 1) vel1 = vel;
        else if (j == 2) vel2 = vel;
        wj *= invd;
        za = zb; sqa = sqb;
        zb = zc; sqb = sqc;
        if (j + 3 < WINN) { zc = ldz(j + 3, row, lane); sqc = ldn(j + 3, row); }
    }

    const float alpha = __ldg(alpha_p);
    F4 zl = za; float sql = sqa;
#pragma unroll
    for (int k = 0; k < NPREDK; ++k) {
        F4 v = { avg.x * alpha, avg.y * alpha, avg.z * alpha, avg.w * alpha };
        F4 zn; float sqn;
        expmap_s(zl, sql, v, zn, sqn);

        float n  = sqrtf(fmaxf(sqn, EPS2));
        float sc = atanhf(fminf(n, CLIPC)) / n;
        const size_t m = (size_t)k * NROWS + row;
        uint32_t h0, h1, l0, l1;
        split4(zn.x * sc, zn.y * sc, zn.z * sc, zn.w * sc, h0, h1, l0, l1);
        size_t off = m * DDIM + lane * 4;
        *reinterpret_cast<uint2*>(g_Ah + off) = make_uint2(h0, h1);
        *reinterpret_cast<uint2*>(g_Al + off) = make_uint2(l0, l1);

        if (k < 3) {
            F4 vn = logmap_s(zl, sql, zn, sqn);
            F4 vk = (k == 0 ? vel0 : (k == 1 ? vel1 : vel2));
            avg.x = (avg.x - w0 * vk.x) * DECAYF + w13 * vn.x;
            avg.y = (avg.y - w0 * vk.y) * DECAYF + w13 * vn.y;
            avg.z = (avg.z - w0 * vk.z) * DECAYF + w13 * vn.z;
            avg.w = (avg.w - w0 * vk.w) * DECAYF + w13 * vn.w;
        }
        zl = zn; sql = sqn;
    }
}

// ============================================================================
#define SM_AH 0
#define SM_AL 16384
#define MLP_SMEM 32768

__global__ void __launch_bounds__(256, 2)
mlp_mma_kernel(const float* __restrict__ b1, const float* __restrict__ b2,
               float* __restrict__ out)
{
    extern __shared__ char smem[];
    const uint32_t sbase = smem_to_u32(smem);
    const int tid  = threadIdx.x;
    const int lane = tid & 31;
    const int wid  = tid >> 5;
    const int mg   = wid >> 1;
    const int ng   = wid & 1;
    const int m0   = blockIdx.x * 64;

    {
        const uint4* gah = reinterpret_cast<const uint4*>(&g_Ah[(size_t)m0 * DDIM]);
        const uint4* gal = reinterpret_cast<const uint4*>(&g_Al[(size_t)m0 * DDIM]);
#pragma unroll
        for (int i = tid; i < 1024; i += 256) {
            int r = i >> 4, kc = i & 15;
            uint32_t off = (uint32_t)(r * 256 + ((kc * 16) ^ ((r & 7) << 4)));
            *reinterpret_cast<uint4*>(smem + SM_AH + off) = __ldg(gah + i);
            *reinterpret_cast<uint4*>(smem + SM_AL + off) = __ldg(gal + i);
        }
    }
    __syncthreads();

    const int rA = mg * 16 + (lane & 15);
    const uint32_t tmask_a = (uint32_t)((((lane >> 4) << 4)) ^ ((rA & 7) << 4));
    const uint32_t abase_h = sbase + SM_AH + rA * 256;
    const uint32_t abase_l = sbase + SM_AL + rA * 256;

    float cacc[3][4];
#pragma unroll
    for (int t = 0; t < 3; ++t)
#pragma unroll
        for (int q = 0; q < 4; ++q) cacc[t][q] = 0.0f;

#pragma unroll
    for (int nc = 0; nc < 4; ++nc) {
        float acc[8][4];
#pragma unroll
        for (int nt = 0; nt < 8; ++nt)
#pragma unroll
            for (int q = 0; q < 4; ++q) acc[nt][q] = 0.0f;

        const uint4* btab = &g_B1f[((size_t)nc * 8) * 16 * 32 + ng * 8 * 32 + lane];
#pragma unroll
        for (int ks = 0; ks < 8; ++ks) {
            const uint32_t xo = (uint32_t)(ks * 32);
            uint32_t ah[4], al[4];
            ldsm4(ah, abase_h + (xo ^ tmask_a));
            ldsm4(al, abase_l + (xo ^ tmask_a));
            const uint4* bk = btab + (size_t)ks * 16 * 32;
#pragma unroll
            for (int nt = 0; nt < 8; ++nt) {
                uint4 e = __ldg(bk + nt * 32);
                mma_bf16(acc[nt], ah, e.x, e.y);
                mma_bf16(acc[nt], al, e.x, e.y);
                mma_bf16(acc[nt], ah, e.z, e.w);
            }
        }

        const int kb0 = nc * 8 + ng * 4;
#pragma unroll
        for (int ks = 0; ks < 4; ++ks) {
            uint32_t ah[4], al[4];
#pragma unroll
            for (int half = 0; half < 2; ++half) {
                int nt = 2 * ks + half;
                int cB = ng * 64 + nt * 8 + 2 * (lane & 3);
                float2 b1v = __ldg(reinterpret_cast<const float2*>(&b1[nc * 128 + cB]));
                float h0 = fmaxf(acc[nt][0] + b1v.x, 0.0f);
                float h1 = fmaxf(acc[nt][1] + b1v.y, 0.0f);
                float h2 = fmaxf(acc[nt][2] + b1v.x, 0.0f);
                float h3 = fmaxf(acc[nt][3] + b1v.y, 0.0f);
                uint32_t p0, p1, q0, q1;
                split4(h0, h1, h2, h3, p0, p1, q0, q1);
                ah[2*half]     = p0;
                ah[2*half + 1] = p1;
                al[2*half]     = q0;
                al[2*half + 1] = q1;
            }
#pragma unroll
            for (int t = 0; t < 3; ++t) {
                uint4 bw = __ldg(&g_W2f[((kb0 + ks) * 3 + t) * 32 + lane]);
                mma_bf16(cacc[t], ah, bw.x, bw.y);
                mma_bf16(cacc[t], al, bw.x, bw.y);
                mma_bf16(cacc[t], ah, bw.z, bw.w);
            }
        }
    }

    __syncthreads();
    float* P1 = reinterpret_cast<float*>(smem);
    float* Rb = reinterpret_cast<float*>(smem + 8192);
    const int r0 = mg * 16 + (lane >> 2);
    if (ng == 1) {
#pragma unroll
        for (int t = 0; t < 3; ++t) {
            int j0 = t * 8 + 2 * (lane & 3);
            P1[r0 * 26 + j0]           = cacc[t][0];
            P1[r0 * 26 + j0 + 1]       = cacc[t][1];
            P1[(r0 + 8) * 26 + j0]     = cacc[t][2];
            P1[(r0 + 8) * 26 + j0 + 1] = cacc[t][3];
        }
    }
    __syncthreads();
    if (ng == 0) {
#pragma unroll
        for (int t = 0; t < 3; ++t) {
            int j0 = t * 8 + 2 * (lane & 3);
            Rb[r0 * 26 + j0]           = cacc[t][0] + P1[r0 * 26 + j0];
            Rb[r0 * 26 + j0 + 1]       = cacc[t][1] + P1[r0 * 26 + j0 + 1];
            Rb[(r0 + 8) * 26 + j0]     = cacc[t][2] + P1[(r0 + 8) * 26 + j0];
            Rb[(r0 + 8) * 26 + j0 + 1] = cacc[t][3] + P1[(r0 + 8) * 26 + j0 + 1];
        }
    }
    __syncthreads();

    {
        const int kidx = m0 >> 14;
        const int bf0  = m0 & 16383;
        const int bb   = bf0 >> 7;
        const int f0   = bf0 & 127;
#pragma unroll
        for (int i = tid; i < 1536; i += 256) {
            int j = i >> 6, f = i & 63;
            out[((size_t)bb * 96 + kidx * 24 + j) * 128 + f0 + f] =
                Rb[f * 26 + j] + __ldg(&b2[j]);
        }
    }
}

// ============================================================================
extern "C" void kernel_launch(void* const* d_in, const int* in_sizes, int n_in,
                              void* d_out, int out_size) {
    const float* trend   = (const float*)d_in[0];
    const float* scoarse = (const float*)d_in[1];
    const float* sfine   = (const float*)d_in[2];
    const float* resid   = (const float*)d_in[3];
    const float* W_t = (const float*)d_in[4];
    const float* b_t = (const float*)d_in[5];
    const float* W_c = (const float*)d_in[6];
    const float* b_c = (const float*)d_in[7];
    const float* W_f = (const float*)d_in[8];
    const float* b_f = (const float*)d_in[9];
    const float* W_r = (const float*)d_in[10];
    const float* b_r = (const float*)d_in[11];
    const float* alpha = (const float*)d_in[12];
    const float* W1 = (const float*)d_in[13];
    const float* b1 = (const float*)d_in[14];
    const float* W2 = (const float*)d_in[15];
    const float* b2 = (const float*)d_in[16];

    cudaFuncSetAttribute(mlp_mma_kernel,
                         cudaFuncAttributeMaxDynamicSharedMemorySize, MLP_SMEM);
    cudaFuncSetAttribute(gemv_mma_kernel,
                         cudaFuncAttributeMaxDynamicSharedMemorySize, GEMV_SMEM);

    prep_kernel<<<88, 256>>>(W1, W2, W_t, W_c, W_f, W_r);
    gemv_mma_kernel<<<1920, 256, GEMV_SMEM>>>(trend, scoarse, sfine, resid,
                                              b_t, b_c, b_f, b_r);
    chain_kernel<<<NROWS / 8, 256>>>(alpha);
    mlp_mma_kernel<<<MTOT / 64, 256, MLP_SMEM>>>(b1, b2, (float*)d_out);
}

// round 15
// speedup vs baseline: 1.6479x; 1.1272x over previous
#include <cuda_runtime.h>
#include <cuda_bf16.h>
#include <cuda_fp16.h>
#include <cstdint>

#define BATCH   128
#define LTOT    720
#define FEAT    128
#define SEGL    24
#define WINN    15
#define NPREDK  4
#define DDIM    128
#define HDIM    512
#define NROWS   (BATCH*FEAT)
#define MTOT    (NPREDK*NROWS)
#define EPSC    1e-6f
#define EPS2    1e-12f
#define MAXNC   0.99999f
#define CLIPC   0.99999988f
#define DECAYF  0.9f

__device__ float g_z[(size_t)WINN * NROWS * DDIM];
__device__ float g_zn[(size_t)WINN * NROWS];
__device__ __align__(16) __half g_Ah[(size_t)MTOT * DDIM];   // MLP A hi (fp16)
__device__ __align__(16) __half g_Al[(size_t)MTOT * DDIM];   // MLP A lo (fp16)
// W1 B-fragment table (single fp16): [nc=4][ks=8][nt=16][lane=32] uint2={b0,b1}
__device__ __align__(16) uint2 g_B1f[4 * 8 * 16 * 32];
// W2 B-fragment table (single fp16): [kb=32][ntile=3][lane=32]
__device__ __align__(16) uint2 g_W2f[32 * 3 * 32];
// tan combined-weight B-fragment table (bf16 hi/lo, unchanged): [ks=6][t=16][lane=32]
__device__ __align__(16) uint4 g_Gf[6 * 16 * 32];

static __device__ __forceinline__ uint32_t smem_to_u32(const void* p) {
    uint32_t a;
    asm("{ .reg .u64 t; cvta.to.shared.u64 t, %1; cvt.u32.u64 %0, t; }"
        : "=r"(a) : "l"(p));
    return a;
}
static __device__ __forceinline__ void ldsm4(uint32_t r[4], uint32_t addr) {
    asm volatile("ldmatrix.sync.aligned.m8n8.x4.shared.b16 {%0,%1,%2,%3}, [%4];"
                 : "=r"(r[0]), "=r"(r[1]), "=r"(r[2]), "=r"(r[3]) : "r"(addr));
}
static __device__ __forceinline__ void ldsm4t(uint32_t r[4], uint32_t addr) {
    asm volatile("ldmatrix.sync.aligned.m8n8.x4.trans.shared.b16 {%0,%1,%2,%3}, [%4];"
                 : "=r"(r[0]), "=r"(r[1]), "=r"(r[2]), "=r"(r[3]) : "r"(addr));
}
static __device__ __forceinline__ void mma_bf16(float d[4], const uint32_t a[4],
                                                uint32_t b0, uint32_t b1) {
    asm volatile(
        "mma.sync.aligned.m16n8k16.row.col.f32.bf16.bf16.f32 "
        "{%0,%1,%2,%3}, {%4,%5,%6,%7}, {%8,%9}, {%0,%1,%2,%3};"
        : "+f"(d[0]), "+f"(d[1]), "+f"(d[2]), "+f"(d[3])
        : "r"(a[0]), "r"(a[1]), "r"(a[2]), "r"(a[3]), "r"(b0), "r"(b1));
}
static __device__ __forceinline__ void mma_f16(float d[4], const uint32_t a[4],
                                               uint32_t b0, uint32_t b1) {
    asm volatile(
        "mma.sync.aligned.m16n8k16.row.col.f32.f16.f16.f32 "
        "{%0,%1,%2,%3}, {%4,%5,%6,%7}, {%8,%9}, {%0,%1,%2,%3};"
        : "+f"(d[0]), "+f"(d[1]), "+f"(d[2]), "+f"(d[3])
        : "r"(a[0]), "r"(a[1]), "r"(a[2]), "r"(a[3]), "r"(b0), "r"(b1));
}
static __device__ __forceinline__ uint32_t bits2(__nv_bfloat162 v) {
    return *reinterpret_cast<uint32_t*>(&v);
}
static __device__ __forceinline__ uint32_t bits2h(__half2 v) {
    return *reinterpret_cast<uint32_t*>(&v);
}

static __device__ __forceinline__ float wred(float v) {
#pragma unroll
    for (int o = 16; o > 0; o >>= 1) v += __shfl_xor_sync(0xffffffffu, v, o);
    return v;
}
static __device__ __forceinline__ void wred2(float &a, float &b) {
#pragma unroll
    for (int o = 16; o > 0; o >>= 1) {
        float ta = __shfl_xor_sync(0xffffffffu, a, o);
        float tb = __shfl_xor_sync(0xffffffffu, b, o);
        a += ta; b += tb;
    }
}

struct F4 { float x, y, z, w; };

static __device__ __forceinline__ float dot4(const F4 &a, const F4 &b) {
    return a.x*b.x + a.y*b.y + a.z*b.z + a.w*b.w;
}

// logmap with SCALAR ||d||^2: one warp reduction (xy).
static __device__ __forceinline__ F4 logmap_s(const F4 &x, float sqx,
                                              const F4 &y, float sqy) {
    float xy  = wred(dot4(x, y));
    float txy = -2.0f * xy;
    float cx  = 1.0f + txy + sqy;
    float cy  = 1.0f - sqx;
    float den = fmaxf(1.0f + txy + sqx*sqy, EPSC);
    float inv = 1.0f / den;
    float sqd = inv*inv * (cy*cy*sqy - 2.0f*cy*cx*xy + cx*cx*sqx);
    float nd  = sqrtf(fmaxf(sqd, EPS2));
    float s   = fmaxf(cy, EPSC) * atanhf(fminf(nd, CLIPC)) / nd * inv;
    F4 r = { (cy*y.x - cx*x.x) * s, (cy*y.y - cx*x.y) * s,
             (cy*y.z - cx*x.z) * s, (cy*y.w - cx*x.w) * s };
    return r;
}

// expmap with scalar ||r||^2: two independent (interleaved) reductions.
static __device__ __forceinline__ void expmap_s(const F4 &x, float sqx, const F4 &v,
                                                F4 &zout, float &sqout) {
    float pa = dot4(v, v);
    float pb = dot4(x, v);
    wred2(pa, pb);
    float m   = fmaxf(1.0f - sqx, EPSC);
    float nv  = sqrtf(fmaxf(pa, EPS2));
    float th  = tanhf(nv / m);
    float sc  = th / nv;
    float xy  = sc * pb;
    float y2  = sc * sc * pa;
    float ca  = 1.0f + 2.0f*xy + y2;
    float cb  = 1.0f - sqx;
    float den = fmaxf(1.0f + 2.0f*xy + sqx*y2, EPSC);
    float inv = 1.0f / den;
    float cbs = cb * sc;
    F4 r = { (ca*x.x + cbs*v.x)*inv, (ca*x.y + cbs*v.y)*inv,
             (ca*x.z + cbs*v.z)*inv, (ca*x.w + cbs*v.w)*inv };
    float sqr = inv*inv * (ca*ca*sqx + 2.0f*ca*cb*xy + cb*cb*y2);
    float nr  = sqrtf(fmaxf(sqr, EPS2));
    if (nr > MAXNC) {
        float s = MAXNC / nr;
        r.x *= s; r.y *= s; r.z *= s; r.w *= s;
        sqr *= s * s;
    }
    zout = r; sqout = sqr;
}

// bf16 hi/lo split (gemv A staging -- unchanged)
static __device__ __forceinline__ void split4(float v0, float v1, float v2, float v3,
                                              uint32_t &h0, uint32_t &h1,
                                              uint32_t &l0, uint32_t &l1) {
    __nv_bfloat162 a = __floats2bfloat162_rn(v0, v1);
    __nv_bfloat162 b = __floats2bfloat162_rn(v2, v3);
    float e0 = v0 - __bfloat162float(__low2bfloat16(a));
    float e1 = v1 - __bfloat162float(__high2bfloat16(a));
    float e2 = v2 - __bfloat162float(__low2bfloat16(b));
    float e3 = v3 - __bfloat162float(__high2bfloat16(b));
    __nv_bfloat162 c = __floats2bfloat162_rn(e0, e1);
    __nv_bfloat162 d = __floats2bfloat162_rn(e2, e3);
    h0 = bits2(a); h1 = bits2(b); l0 = bits2(c); l1 = bits2(d);
}

// fp16 hi/lo split (MLP path)
static __device__ __forceinline__ void split4h(float v0, float v1, float v2, float v3,
                                               uint32_t &h0, uint32_t &h1,
                                               uint32_t &l0, uint32_t &l1) {
    __half2 a = __floats2half2_rn(v0, v1);
    __half2 b = __floats2half2_rn(v2, v3);
    float e0 = v0 - __low2float(a);
    float e1 = v1 - __high2float(a);
    float e2 = v2 - __low2float(b);
    float e3 = v3 - __high2float(b);
    __half2 c = __floats2half2_rn(e0, e1);
    __half2 d = __floats2half2_rn(e2, e3);
    h0 = bits2h(a); h1 = bits2h(b); l0 = bits2h(c); l1 = bits2h(d);
}

// ============================================================================
// Merged prep kernel.
// ============================================================================
__global__ void prep_kernel(const float* __restrict__ W1, const float* __restrict__ W2,
                            const float* __restrict__ W_t, const float* __restrict__ W_c,
                            const float* __restrict__ W_f, const float* __restrict__ W_r)
{
    int idx = blockIdx.x * 256 + threadIdx.x;
    if (idx < 16384) {
        int lane = idx & 31;
        int nt   = (idx >> 5) & 15;
        int ks   = (idx >> 9) & 7;
        int nc   = idx >> 12;
        int n    = nc * 128 + nt * 8 + (lane >> 2);
        int k0   = ks * 16 + 2 * (lane & 3);
        float w00 = __ldg(&W1[(size_t)(k0    ) * HDIM + n]);
        float w01 = __ldg(&W1[(size_t)(k0 + 1) * HDIM + n]);
        float w08 = __ldg(&W1[(size_t)(k0 + 8) * HDIM + n]);
        float w09 = __ldg(&W1[(size_t)(k0 + 9) * HDIM + n]);
        uint2 v;
        v.x = bits2h(__floats2half2_rn(w00, w01));
        v.y = bits2h(__floats2half2_rn(w08, w09));
        g_B1f[idx] = v;
    } else if (idx < 16384 + 3072) {
        int e = idx - 16384;
        int lane = e & 31;
        int t    = (e >> 5) % 3;
        int kb   = e / 96;
        int k0   = kb * 16 + 2 * (lane & 3);
        int n    = t * 8 + (lane >> 2);
        float w00 = __ldg(&W2[(size_t)(k0    ) * 24 + n]);
        float w01 = __ldg(&W2[(size_t)(k0 + 1) * 24 + n]);
        float w08 = __ldg(&W2[(size_t)(k0 + 8) * 24 + n]);
        float w09 = __ldg(&W2[(size_t)(k0 + 9) * 24 + n]);
        uint2 v;
        v.x = bits2h(__floats2half2_rn(w00, w01));
        v.y = bits2h(__floats2half2_rn(w08, w09));
        g_W2f[(kb * 3 + t) * 32 + lane] = v;
    } else if (idx < 19456 + 3072) {
        int e = idx - 19456;
        int lane = e & 31;
        int t    = (e >> 5) & 15;
        int ks   = e >> 9;
        int d    = t * 8 + (lane >> 2);
        int k0   = ks * 16 + 2 * (lane & 3);
        float vv[4];
        int kk[4] = { k0, k0 + 1, k0 + 8, k0 + 9 };
#pragma unroll
        for (int q = 0; q < 4; ++q) {
            int k = kk[q];
            int st = k / 24, s = k - st * 24;
            const float* W = (st == 0 ? W_t : st == 1 ? W_c :
                              st == 2 ? W_f : W_r);
            vv[q] = __ldg(&W[s * DDIM + d]);
        }
        uint4 v;
        split4(vv[0], vv[1], vv[2], vv[3], v.x, v.y, v.z, v.w);
        g_Gf[(ks * 16 + t) * 32 + lane] = v;
    }
}

// ============================================================================
// Kernel 1a: tan GEMM on tensor cores + fused expmap0 (bf16 3-term, unchanged)
// ============================================================================
#define SM2_AH   0
#define SM2_AL   26112
#define SM2_P    52224
#define SM2_BIAS 53248
#define GEMV_SMEM (53248 + 512)

__global__ void __launch_bounds__(256, 2)
gemv_mma_kernel(const float* __restrict__ trend,  const float* __restrict__ scoarse,
                const float* __restrict__ sfine,  const float* __restrict__ resid,
                const float* __restrict__ b_t, const float* __restrict__ b_c,
                const float* __restrict__ b_f, const float* __restrict__ b_r)
{
    extern __shared__ char smem[];
    const uint32_t sbase = smem_to_u32(smem);
    const int tid  = threadIdx.x;
    const int lane = tid & 31;
    const int wid  = tid >> 5;
    const int mg   = wid >> 1;
    const int ng   = wid & 1;
    const int b    = blockIdx.x / 15;
    const int slot = blockIdx.x - b * 15;

    float* sPart = reinterpret_cast<float*>(smem + SM2_P);
    float* sBias = reinterpret_cast<float*>(smem + SM2_BIAS);

    if (tid < 128)
        sBias[tid] = __ldg(&b_t[tid]) + __ldg(&b_c[tid]) +
                     __ldg(&b_f[tid]) + __ldg(&b_r[tid]);

    const size_t base_b = (size_t)b * LTOT * FEAT;
#pragma unroll
    for (int it = 0; it < 12; ++it) {
        int i  = tid + it * 256;
        int k  = i >> 5;
        int c4 = i & 31;
        int st = k / 24, s = k - st * 24;
        const float* src = (st == 0 ? trend : st == 1 ? scoarse :
                            st == 2 ? sfine : resid);
        float4 v = __ldg(reinterpret_cast<const float4*>(
            &src[base_b + (size_t)(360 + slot * 24 + s) * FEAT]) + c4);
        uint32_t h0, h1, l0, l1;
        split4(v.x, v.y, v.z, v.w, h0, h1, l0, l1);
        uint32_t off = (uint32_t)(k * 136 + c4 * 4) * 2;
        *reinterpret_cast<uint2*>(smem + SM2_AH + off) = make_uint2(h0, h1);
        *reinterpret_cast<uint2*>(smem + SM2_AL + off) = make_uint2(l0, l1);
    }
    __syncthreads();

    uint32_t aoffh[2], aoffl[2];
    {
        int kRow = (lane & 7) + ((lane >> 4) << 3);
        int mC8  = ((lane >> 3) & 1) << 3;
#pragma unroll
        for (int mt = 0; mt < 2; ++mt) {
            uint32_t off = (uint32_t)(kRow * 136 + mg * 32 + mt * 16 + mC8) * 2;
            aoffh[mt] = sbase + SM2_AH + off;
            aoffl[mt] = sbase + SM2_AL + off;
        }
    }

    float acc[2][8][4];
#pragma unroll
    for (int mt = 0; mt < 2; ++mt)
#pragma unroll
        for (int nt = 0; nt < 8; ++nt)
#pragma unroll
            for (int q = 0; q < 4; ++q) acc[mt][nt][q] = 0.0f;

#pragma unroll
    for (int ks = 0; ks < 6; ++ks) {
        uint32_t ah[2][4], al[2][4];
        ldsm4t(ah[0], aoffh[0] + ks * 16 * 272);
        ldsm4t(ah[1], aoffh[1] + ks * 16 * 272);
        ldsm4t(al[0], aoffl[0] + ks * 16 * 272);
        ldsm4t(al[1], aoffl[1] + ks * 16 * 272);
#pragma unroll
        for (int g4 = 0; g4 < 4; ++g4) {
            const int t0 = ng * 8 + 2 * g4;
            uint4 e0 = __ldg(&g_Gf[(ks * 16 + t0) * 32 + lane]);
            uint4 e1 = __ldg(&g_Gf[(ks * 16 + t0 + 1) * 32 + lane]);
#pragma unroll
            for (int mt = 0; mt < 2; ++mt) {
                mma_bf16(acc[mt][2*g4],   ah[mt], e0.x, e0.y);
                mma_bf16(acc[mt][2*g4+1], ah[mt], e1.x, e1.y);
                mma_bf16(acc[mt][2*g4],   al[mt], e0.x, e0.y);
                mma_bf16(acc[mt][2*g4+1], al[mt], e1.x, e1.y);
                mma_bf16(acc[mt][2*g4],   ah[mt], e0.z, e0.w);
                mma_bf16(acc[mt][2*g4+1], ah[mt], e1.z, e1.w);
            }
        }
    }

    float p[2][2];
#pragma unroll
    for (int mt = 0; mt < 2; ++mt) { p[mt][0] = 0.0f; p[mt][1] = 0.0f; }
#pragma unroll
    for (int nt = 0; nt < 8; ++nt) {
        int c = ng * 64 + nt * 8 + 2 * (lane & 3);
        float bx = sBias[c], by = sBias[c + 1];
#pragma unroll
        for (int mt = 0; mt < 2; ++mt) {
            acc[mt][nt][0] += bx; acc[mt][nt][1] += by;
            acc[mt][nt][2] += bx; acc[mt][nt][3] += by;
            p[mt][0] += acc[mt][nt][0]*acc[mt][nt][0] + acc[mt][nt][1]*acc[mt][nt][1];
            p[mt][1] += acc[mt][nt][2]*acc[mt][nt][2] + acc[mt][nt][3]*acc[mt][nt][3];
        }
    }
#pragma unroll
    for (int mt = 0; mt < 2; ++mt) {
#pragma unroll
        for (int h = 0; h < 2; ++h) {   // quad-local reduction ONLY
            p[mt][h] += __shfl_xor_sync(0xffffffffu, p[mt][h], 1);
            p[mt][h] += __shfl_xor_sync(0xffffffffu, p[mt][h], 2);
        }
        if ((lane & 3) == 0) {
            int r0 = mg * 32 + mt * 16 + (lane >> 2);
            sPart[r0 * 2 + ng]       = p[mt][0];
            sPart[(r0 + 8) * 2 + ng] = p[mt][1];
        }
    }
    __syncthreads();

    float* gz = &g_z[((size_t)slot * NROWS + (size_t)b * 128) * DDIM];
    float* gn = &g_zn[(size_t)slot * NROWS + (size_t)b * 128];
#pragma unroll
    for (int mt = 0; mt < 2; ++mt) {
        int r0 = mg * 32 + mt * 16 + (lane >> 2);
        float sq0 = sPart[r0 * 2] + sPart[r0 * 2 + 1];
        float sq1 = sPart[(r0 + 8) * 2] + sPart[(r0 + 8) * 2 + 1];
        float n0 = sqrtf(fmaxf(sq0, EPS2));
        float n1 = sqrtf(fmaxf(sq1, EPS2));
        float t0 = tanhf(n0), t1 = tanhf(n1);
        float sc0 = (t0 > MAXNC ? MAXNC : t0) / n0;
        float sc1 = (t1 > MAXNC ? MAXNC : t1) / n1;
        if (ng == 0 && (lane & 3) == 0) {
            gn[r0]     = sq0 * sc0 * sc0;
            gn[r0 + 8] = sq1 * sc1 * sc1;
        }
#pragma unroll
        for (int nt = 0; nt < 8; ++nt) {
            int c = ng * 64 + nt * 8 + 2 * (lane & 3);
            *reinterpret_cast<float2*>(&gz[r0 * 128 + c]) =
                make_float2(acc[mt][nt][0] * sc0, acc[mt][nt][1] * sc0);
            *reinterpret_cast<float2*>(&gz[(r0 + 8) * 128 + c]) =
                make_float2(acc[mt][nt][2] * sc1, acc[mt][nt][3] * sc1);
        }
    }
}

// ============================================================================
// Kernel 1b: hyperbolic chain; emits fp16 hi/lo split of t0.
// ============================================================================
static __device__ __forceinline__ F4 ldz(int slot, int row, int lane) {
    float4 v = __ldg(reinterpret_cast<const float4*>(
        &g_z[((size_t)slot * NROWS + row) * DDIM + lane * 4]));
    F4 r = { v.x, v.y, v.z, v.w };
    return r;
}
static __device__ __forceinline__ float ldn(int slot, int row) {
    return __ldg(&g_zn[(size_t)slot * NROWS + row]);
}

__global__ void __launch_bounds__(256, 3)
chain_kernel(const float* __restrict__ alpha_p)
{
    const int tid  = threadIdx.x;
    const int wid  = tid >> 5;
    const int lane = tid & 31;
    const int row  = blockIdx.x * 8 + wid;

    float s = 0.0f, wv = 1.0f;
#pragma unroll
    for (int j = 13; j >= 0; --j) { s += wv; if (j > 0) wv *= DECAYF; }
    const float w0  = wv / s;
    const float w13 = 1.0f / s;
    const float invd = 1.0f / DECAYF;

    F4 za = ldz(0, row, lane);
    F4 zb = ldz(1, row, lane);
    F4 zc = ldz(2, row, lane);
    float sqa = ldn(0, row);
    float sqb = ldn(1, row);
    float sqc = ldn(2, row);

    F4 avg = {0,0,0,0};
    F4 vel0, vel1, vel2;
    float wj = w0;

#pragma unroll
    for (int j = 0; j < 14; ++j) {
        F4 vel = logmap_s(za, sqa, zb, sqb);
        avg.x += wj * vel.x; avg.y += wj * vel.y;
        avg.z += wj * vel.z; avg.w += wj * vel.w;
        if (j == 0) vel0 = vel;
        else if (j == 1) vel1 = vel;
        else if (j == 2) vel2 = vel;
        wj *= invd;
        za = zb; sqa = sqb;
        zb = zc; sqb = sqc;
        if (j + 3 < WINN) { zc = ldz(j + 3, row, lane); sqc = ldn(j + 3, row); }
    }

    const float alpha = __ldg(alpha_p);
    F4 zl = za; float sql = sqa;
#pragma unroll
    for (int k = 0; k < NPREDK; ++k) {
        F4 v = { avg.x * alpha, avg.y * alpha, avg.z * alpha, avg.w * alpha };
        F4 zn; float sqn;
        expmap_s(zl, sql, v, zn, sqn);

        float n  = sqrtf(fmaxf(sqn, EPS2));
        float sc = atanhf(fminf(n, CLIPC)) / n;
        const size_t m = (size_t)k * NROWS + row;
        uint32_t h0, h1, l0, l1;
        split4h(zn.x * sc, zn.y * sc, zn.z * sc, zn.w * sc, h0, h1, l0, l1);
        size_t off = m * DDIM + lane * 4;
        *reinterpret_cast<uint2*>(g_Ah + off) = make_uint2(h0, h1);
        *reinterpret_cast<uint2*>(g_Al + off) = make_uint2(l0, l1);

        if (k < 3) {
            F4 vn = logmap_s(zl, sql, zn, sqn);
            F4 vk = (k == 0 ? vel0 : (k == 1 ? vel1 : vel2));
            avg.x = (avg.x - w0 * vk.x) * DECAYF + w13 * vn.x;
            avg.y = (avg.y - w0 * vk.y) * DECAYF + w13 * vn.y;
            avg.z = (avg.z - w0 * vk.z) * DECAYF + w13 * vn.z;
            avg.w = (avg.w - w0 * vk.w) * DECAYF + w13 * vn.w;
        }
        zl = zn; sql = sqn;
    }
}

// ============================================================================
// Kernel 2: MLP on tensor cores, fp16 2-term split (A/H hi+lo vs single-fp16
// weight tables).  608 mma/warp vs 912 in the bf16 3-term version.
// ============================================================================
#define SM_AH 0
#define SM_AL 16384
#define MLP_SMEM 32768

__global__ void __launch_bounds__(256, 2)
mlp_mma_kernel(const float* __restrict__ b1, const float* __restrict__ b2,
               float* __restrict__ out)
{
    extern __shared__ char smem[];
    const uint32_t sbase = smem_to_u32(smem);
    const int tid  = threadIdx.x;
    const int lane = tid & 31;
    const int wid  = tid >> 5;
    const int mg   = wid >> 1;
    const int ng   = wid & 1;
    const int m0   = blockIdx.x * 64;

    {
        const uint4* gah = reinterpret_cast<const uint4*>(&g_Ah[(size_t)m0 * DDIM]);
        const uint4* gal = reinterpret_cast<const uint4*>(&g_Al[(size_t)m0 * DDIM]);
#pragma unroll
        for (int i = tid; i < 1024; i += 256) {
            int r = i >> 4, kc = i & 15;
            uint32_t off = (uint32_t)(r * 256 + ((kc * 16) ^ ((r & 7) << 4)));
            *reinterpret_cast<uint4*>(smem + SM_AH + off) = __ldg(gah + i);
            *reinterpret_cast<uint4*>(smem + SM_AL + off) = __ldg(gal + i);
        }
    }
    __syncthreads();

    const int rA = mg * 16 + (lane & 15);
    const uint32_t tmask_a = (uint32_t)((((lane >> 4) << 4)) ^ ((rA & 7) << 4));
    const uint32_t abase_h = sbase + SM_AH + rA * 256;
    const uint32_t abase_l = sbase + SM_AL + rA * 256;

    float cacc[3][4];
#pragma unroll
    for (int t = 0; t < 3; ++t)
#pragma unroll
        for (int q = 0; q < 4; ++q) cacc[t][q] = 0.0f;

#pragma unroll
    for (int nc = 0; nc < 4; ++nc) {
        float acc[8][4];
#pragma unroll
        for (int nt = 0; nt < 8; ++nt)
#pragma unroll
            for (int q = 0; q < 4; ++q) acc[nt][q] = 0.0f;

        // ---- GEMM1: Ah*B + Al*B (2 mma), B single fp16 from table ----
        const uint2* btab = &g_B1f[((size_t)nc * 8) * 16 * 32 + ng * 8 * 32 + lane];
#pragma unroll
        for (int ks = 0; ks < 8; ++ks) {
            const uint32_t xo = (uint32_t)(ks * 32);
            uint32_t ah[4], al[4];
            ldsm4(ah, abase_h + (xo ^ tmask_a));
            ldsm4(al, abase_l + (xo ^ tmask_a));
            const uint2* bk = btab + (size_t)ks * 16 * 32;
#pragma unroll
            for (int nt = 0; nt < 8; ++nt) {
                uint2 e = __ldg(bk + nt * 32);
                mma_f16(acc[nt], ah, e.x, e.y);
                mma_f16(acc[nt], al, e.x, e.y);
            }
        }

        // ---- epilogue: bias + relu -> fp16 hi/lo A-frags -> GEMM2 (2 mma) ----
        const int kb0 = nc * 8 + ng * 4;
#pragma unroll
        for (int ks = 0; ks < 4; ++ks) {
            uint32_t ah[4], al[4];
#pragma unroll
            for (int half = 0; half < 2; ++half) {
                int nt = 2 * ks + half;
                int cB = ng * 64 + nt * 8 + 2 * (lane & 3);
                float2 b1v = __ldg(reinterpret_cast<const float2*>(&b1[nc * 128 + cB]));
                float h0 = fmaxf(acc[nt][0] + b1v.x, 0.0f);
                float h1 = fmaxf(acc[nt][1] + b1v.y, 0.0f);
                float h2 = fmaxf(acc[nt][2] + b1v.x, 0.0f);
                float h3 = fmaxf(acc[nt][3] + b1v.y, 0.0f);
                uint32_t p0, p1, q0, q1;
                split4h(h0, h1, h2, h3, p0, p1, q0, q1);
                ah[2*half]     = p0;
                ah[2*half + 1] = p1;
                al[2*half]     = q0;
                al[2*half + 1] = q1;
            }
#pragma unroll
            for (int t = 0; t < 3; ++t) {
                uint2 bw = __ldg(&g_W2f[((kb0 + ks) * 3 + t) * 32 + lane]);
                mma_f16(cacc[t], ah, bw.x, bw.y);
                mma_f16(cacc[t], al, bw.x, bw.y);
            }
        }
    }

    __syncthreads();
    float* P1 = reinterpret_cast<float*>(smem);
    float* Rb = reinterpret_cast<float*>(smem + 8192);
    const int r0 = mg * 16 + (lane >> 2);
    if (ng == 1) {
#pragma unroll
        for (int t = 0; t < 3; ++t) {
            int j0 = t * 8 + 2 * (lane & 3);
            P1[r0 * 26 + j0]           = cacc[t][0];
            P1[r0 * 26 + j0 + 1]       = cacc[t][1];
            P1[(r0 + 8) * 26 + j0]     = cacc[t][2];
            P1[(r0 + 8) * 26 + j0 + 1] = cacc[t][3];
        }
    }
    __syncthreads();
    if (ng == 0) {
#pragma unroll
        for (int t = 0; t < 3; ++t) {
            int j0 = t * 8 + 2 * (lane & 3);
            Rb[r0 * 26 + j0]           = cacc[t][0] + P1[r0 * 26 + j0];
            Rb[r0 * 26 + j0 + 1]       = cacc[t][1] + P1[r0 * 26 + j0 + 1];
            Rb[(r0 + 8) * 26 + j0]     = cacc[t][2] + P1[(r0 + 8) * 26 + j0];
            Rb[(r0 + 8) * 26 + j0 + 1] = cacc[t][3] + P1[(r0 + 8) * 26 + j0 + 1];
        }
    }
    __syncthreads();

    {
        const int kidx = m0 >> 14;
        const int bf0  = m0 & 16383;
        const int bb   = bf0 >> 7;
        const int f0   = bf0 & 127;
#pragma unroll
        for (int i = tid; i < 1536; i += 256) {
            int j = i >> 6, f = i & 63;
            out[((size_t)bb * 96 + kidx * 24 + j) * 128 + f0 + f] =
                Rb[f * 26 + j] + __ldg(&b2[j]);
        }
    }
}

// ============================================================================
extern "C" void kernel_launch(void* const* d_in, const int* in_sizes, int n_in,
                              void* d_out, int out_size) {
    const float* trend   = (const float*)d_in[0];
    const float* scoarse = (const float*)d_in[1];
    const float* sfine   = (const float*)d_in[2];
    const float* resid   = (const float*)d_in[3];
    const float* W_t = (const float*)d_in[4];
    const float* b_t = (const float*)d_in[5];
    const float* W_c = (const float*)d_in[6];
    const float* b_c = (const float*)d_in[7];
    const float* W_f = (const float*)d_in[8];
    const float* b_f = (const float*)d_in[9];
    const float* W_r = (const float*)d_in[10];
    const float* b_r = (const float*)d_in[11];
    const float* alpha = (const float*)d_in[12];
    const float* W1 = (const float*)d_in[13];
    const float* b1 = (const float*)d_in[14];
    const float* W2 = (const float*)d_in[15];
    const float* b2 = (const float*)d_in[16];

    cudaFuncSetAttribute(mlp_mma_kernel,
                         cudaFuncAttributeMaxDynamicSharedMemorySize, MLP_SMEM);
    cudaFuncSetAttribute(gemv_mma_kernel,
                         cudaFuncAttributeMaxDynamicSharedMemorySize, GEMV_SMEM);

    prep_kernel<<<88, 256>>>(W1, W2, W_t, W_c, W_f, W_r);
    gemv_mma_kernel<<<1920, 256, GEMV_SMEM>>>(trend, scoarse, sfine, resid,
                                              b_t, b_c, b_f, b_r);
    chain_kernel<<<NROWS / 8, 256>>>(alpha);
    mlp_mma_kernel<<<MTOT / 64, 256, MLP_SMEM>>>(b1, b2, (float*)d_out);
}

// round 16
// speedup vs baseline: 1.7616x; 1.0690x over previous
#include <cuda_runtime.h>
#include <cuda_bf16.h>
#include <cuda_fp16.h>
#include <cstdint>

#define BATCH   128
#define LTOT    720
#define FEAT    128
#define SEGL    24
#define WINN    15
#define NPREDK  4
#define DDIM    128
#define HDIM    512
#define NROWS   (BATCH*FEAT)
#define MTOT    (NPREDK*NROWS)
#define EPSC    1e-6f
#define EPS2    1e-12f
#define MAXNC   0.99999f
#define CLIPC   0.99999988f
#define DECAYF  0.9f

__device__ float g_z[(size_t)WINN * NROWS * DDIM];
__device__ float g_zn[(size_t)WINN * NROWS];
__device__ __align__(16) __half g_Ah[(size_t)MTOT * DDIM];   // MLP A hi (fp16)
__device__ __align__(16) __half g_Al[(size_t)MTOT * DDIM];   // MLP A lo (fp16)
// W1 B-fragment table (single fp16): [nc=4][ks=8][nt=16][lane=32] uint2={b0,b1}
__device__ __align__(16) uint2 g_B1f[4 * 8 * 16 * 32];
// W2 B-fragment table (single fp16): [kb=32][ntile=3][lane=32]
__device__ __align__(16) uint2 g_W2f[32 * 3 * 32];
// tan combined-weight B-fragment table (single fp16): [ks=6][t=16][lane=32]
__device__ __align__(16) uint2 g_Gf[6 * 16 * 32];

static __device__ __forceinline__ uint32_t smem_to_u32(const void* p) {
    uint32_t a;
    asm("{ .reg .u64 t; cvta.to.shared.u64 t, %1; cvt.u32.u64 %0, t; }"
        : "=r"(a) : "l"(p));
    return a;
}
static __device__ __forceinline__ void ldsm4(uint32_t r[4], uint32_t addr) {
    asm volatile("ldmatrix.sync.aligned.m8n8.x4.shared.b16 {%0,%1,%2,%3}, [%4];"
                 : "=r"(r[0]), "=r"(r[1]), "=r"(r[2]), "=r"(r[3]) : "r"(addr));
}
static __device__ __forceinline__ void ldsm4t(uint32_t r[4], uint32_t addr) {
    asm volatile("ldmatrix.sync.aligned.m8n8.x4.trans.shared.b16 {%0,%1,%2,%3}, [%4];"
                 : "=r"(r[0]), "=r"(r[1]), "=r"(r[2]), "=r"(r[3]) : "r"(addr));
}
static __device__ __forceinline__ void mma_f16(float d[4], const uint32_t a[4],
                                               uint32_t b0, uint32_t b1) {
    asm volatile(
        "mma.sync.aligned.m16n8k16.row.col.f32.f16.f16.f32 "
        "{%0,%1,%2,%3}, {%4,%5,%6,%7}, {%8,%9}, {%0,%1,%2,%3};"
        : "+f"(d[0]), "+f"(d[1]), "+f"(d[2]), "+f"(d[3])
        : "r"(a[0]), "r"(a[1]), "r"(a[2]), "r"(a[3]), "r"(b0), "r"(b1));
}
static __device__ __forceinline__ uint32_t bits2h(__half2 v) {
    return *reinterpret_cast<uint32_t*>(&v);
}

static __device__ __forceinline__ float wred(float v) {
#pragma unroll
    for (int o = 16; o > 0; o >>= 1) v += __shfl_xor_sync(0xffffffffu, v, o);
    return v;
}
static __device__ __forceinline__ void wred2(float &a, float &b) {
#pragma unroll
    for (int o = 16; o > 0; o >>= 1) {
        float ta = __shfl_xor_sync(0xffffffffu, a, o);
        float tb = __shfl_xor_sync(0xffffffffu, b, o);
        a += ta; b += tb;
    }
}

struct F4 { float x, y, z, w; };

static __device__ __forceinline__ float dot4(const F4 &a, const F4 &b) {
    return a.x*b.x + a.y*b.y + a.z*b.z + a.w*b.w;
}

static __device__ __forceinline__ F4 logmap_s(const F4 &x, float sqx,
                                              const F4 &y, float sqy) {
    float xy  = wred(dot4(x, y));
    float txy = -2.0f * xy;
    float cx  = 1.0f + txy + sqy;
    float cy  = 1.0f - sqx;
    float den = fmaxf(1.0f + txy + sqx*sqy, EPSC);
    float inv = 1.0f / den;
    float sqd = inv*inv * (cy*cy*sqy - 2.0f*cy*cx*xy + cx*cx*sqx);
    float nd  = sqrtf(fmaxf(sqd, EPS2));
    float s   = fmaxf(cy, EPSC) * atanhf(fminf(nd, CLIPC)) / nd * inv;
    F4 r = { (cy*y.x - cx*x.x) * s, (cy*y.y - cx*x.y) * s,
             (cy*y.z - cx*x.z) * s, (cy*y.w - cx*x.w) * s };
    return r;
}

static __device__ __forceinline__ void expmap_s(const F4 &x, float sqx, const F4 &v,
                                                F4 &zout, float &sqout) {
    float pa = dot4(v, v);
    float pb = dot4(x, v);
    wred2(pa, pb);
    float m   = fmaxf(1.0f - sqx, EPSC);
    float nv  = sqrtf(fmaxf(pa, EPS2));
    float th  = tanhf(nv / m);
    float sc  = th / nv;
    float xy  = sc * pb;
    float y2  = sc * sc * pa;
    float ca  = 1.0f + 2.0f*xy + y2;
    float cb  = 1.0f - sqx;
    float den = fmaxf(1.0f + 2.0f*xy + sqx*y2, EPSC);
    float inv = 1.0f / den;
    float cbs = cb * sc;
    F4 r = { (ca*x.x + cbs*v.x)*inv, (ca*x.y + cbs*v.y)*inv,
             (ca*x.z + cbs*v.z)*inv, (ca*x.w + cbs*v.w)*inv };
    float sqr = inv*inv * (ca*ca*sqx + 2.0f*ca*cb*xy + cb*cb*y2);
    float nr  = sqrtf(fmaxf(sqr, EPS2));
    if (nr > MAXNC) {
        float s = MAXNC / nr;
        r.x *= s; r.y *= s; r.z *= s; r.w *= s;
        sqr *= s * s;
    }
    zout = r; sqout = sqr;
}

// fp16 hi/lo split
static __device__ __forceinline__ void split4h(float v0, float v1, float v2, float v3,
                                               uint32_t &h0, uint32_t &h1,
                                               uint32_t &l0, uint32_t &l1) {
    __half2 a = __floats2half2_rn(v0, v1);
    __half2 b = __floats2half2_rn(v2, v3);
    float e0 = v0 - __low2float(a);
    float e1 = v1 - __high2float(a);
    float e2 = v2 - __low2float(b);
    float e3 = v3 - __high2float(b);
    __half2 c = __floats2half2_rn(e0, e1);
    __half2 d = __floats2half2_rn(e2, e3);
    h0 = bits2h(a); h1 = bits2h(b); l0 = bits2h(c); l1 = bits2h(d);
}

// ============================================================================
// Merged prep kernel (all weight tables single fp16).
// ============================================================================
__global__ void prep_kernel(const float* __restrict__ W1, const float* __restrict__ W2,
                            const float* __restrict__ W_t, const float* __restrict__ W_c,
                            const float* __restrict__ W_f, const float* __restrict__ W_r)
{
    int idx = blockIdx.x * 256 + threadIdx.x;
    if (idx < 16384) {
        int lane = idx & 31;
        int nt   = (idx >> 5) & 15;
        int ks   = (idx >> 9) & 7;
        int nc   = idx >> 12;
        int n    = nc * 128 + nt * 8 + (lane >> 2);
        int k0   = ks * 16 + 2 * (lane & 3);
        float w00 = __ldg(&W1[(size_t)(k0    ) * HDIM + n]);
        float w01 = __ldg(&W1[(size_t)(k0 + 1) * HDIM + n]);
        float w08 = __ldg(&W1[(size_t)(k0 + 8) * HDIM + n]);
        float w09 = __ldg(&W1[(size_t)(k0 + 9) * HDIM + n]);
        uint2 v;
        v.x = bits2h(__floats2half2_rn(w00, w01));
        v.y = bits2h(__floats2half2_rn(w08, w09));
        g_B1f[idx] = v;
    } else if (idx < 16384 + 3072) {
        int e = idx - 16384;
        int lane = e & 31;
        int t    = (e >> 5) % 3;
        int kb   = e / 96;
        int k0   = kb * 16 + 2 * (lane & 3);
        int n    = t * 8 + (lane >> 2);
        float w00 = __ldg(&W2[(size_t)(k0    ) * 24 + n]);
        float w01 = __ldg(&W2[(size_t)(k0 + 1) * 24 + n]);
        float w08 = __ldg(&W2[(size_t)(k0 + 8) * 24 + n]);
        float w09 = __ldg(&W2[(size_t)(k0 + 9) * 24 + n]);
        uint2 v;
        v.x = bits2h(__floats2half2_rn(w00, w01));
        v.y = bits2h(__floats2half2_rn(w08, w09));
        g_W2f[(kb * 3 + t) * 32 + lane] = v;
    } else if (idx < 19456 + 3072) {
        int e = idx - 19456;
        int lane = e & 31;
        int t    = (e >> 5) & 15;
        int ks   = e >> 9;
        int d    = t * 8 + (lane >> 2);
        int k0   = ks * 16 + 2 * (lane & 3);
        float vv[4];
        int kk[4] = { k0, k0 + 1, k0 + 8, k0 + 9 };
#pragma unroll
        for (int q = 0; q < 4; ++q) {
            int k = kk[q];
            int st = k / 24, s = k - st * 24;
            const float* W = (st == 0 ? W_t : st == 1 ? W_c :
                              st == 2 ? W_f : W_r);
            vv[q] = __ldg(&W[s * DDIM + d]);
        }
        uint2 v;
        v.x = bits2h(__floats2half2_rn(vv[0], vv[1]));
        v.y = bits2h(__floats2half2_rn(vv[2], vv[3]));
        g_Gf[(ks * 16 + t) * 32 + lane] = v;
    }
}

// ============================================================================
// Kernel 1a: tan GEMM (fp16 2-term) + fused expmap0 -> g_z (+ norms g_zn).
// ============================================================================
#define SM2_AH   0
#define SM2_AL   26112
#define SM2_P    52224
#define SM2_BIAS 53248
#define GEMV_SMEM (53248 + 512)

__global__ void __launch_bounds__(256, 2)
gemv_mma_kernel(const float* __restrict__ trend,  const float* __restrict__ scoarse,
                const float* __restrict__ sfine,  const float* __restrict__ resid,
                const float* __restrict__ b_t, const float* __restrict__ b_c,
                const float* __restrict__ b_f, const float* __restrict__ b_r)
{
    extern __shared__ char smem[];
    const uint32_t sbase = smem_to_u32(smem);
    const int tid  = threadIdx.x;
    const int lane = tid & 31;
    const int wid  = tid >> 5;
    const int mg   = wid >> 1;
    const int ng   = wid & 1;
    const int b    = blockIdx.x / 15;
    const int slot = blockIdx.x - b * 15;

    float* sPart = reinterpret_cast<float*>(smem + SM2_P);
    float* sBias = reinterpret_cast<float*>(smem + SM2_BIAS);

    if (tid < 128)
        sBias[tid] = __ldg(&b_t[tid]) + __ldg(&b_c[tid]) +
                     __ldg(&b_f[tid]) + __ldg(&b_r[tid]);

    // ---- stage A^T hi/lo (fp16) ----
    const size_t base_b = (size_t)b * LTOT * FEAT;
#pragma unroll
    for (int it = 0; it < 12; ++it) {
        int i  = tid + it * 256;
        int k  = i >> 5;
        int c4 = i & 31;
        int st = k / 24, s = k - st * 24;
        const float* src = (st == 0 ? trend : st == 1 ? scoarse :
                            st == 2 ? sfine : resid);
        float4 v = __ldg(reinterpret_cast<const float4*>(
            &src[base_b + (size_t)(360 + slot * 24 + s) * FEAT]) + c4);
        uint32_t h0, h1, l0, l1;
        split4h(v.x, v.y, v.z, v.w, h0, h1, l0, l1);
        uint32_t off = (uint32_t)(k * 136 + c4 * 4) * 2;
        *reinterpret_cast<uint2*>(smem + SM2_AH + off) = make_uint2(h0, h1);
        *reinterpret_cast<uint2*>(smem + SM2_AL + off) = make_uint2(l0, l1);
    }
    __syncthreads();

    uint32_t aoffh[2], aoffl[2];
    {
        int kRow = (lane & 7) + ((lane >> 4) << 3);
        int mC8  = ((lane >> 3) & 1) << 3;
#pragma unroll
        for (int mt = 0; mt < 2; ++mt) {
            uint32_t off = (uint32_t)(kRow * 136 + mg * 32 + mt * 16 + mC8) * 2;
            aoffh[mt] = sbase + SM2_AH + off;
            aoffl[mt] = sbase + SM2_AL + off;
        }
    }

    float acc[2][8][4];
#pragma unroll
    for (int mt = 0; mt < 2; ++mt)
#pragma unroll
        for (int nt = 0; nt < 8; ++nt)
#pragma unroll
            for (int q = 0; q < 4; ++q) acc[mt][nt][q] = 0.0f;

#pragma unroll
    for (int ks = 0; ks < 6; ++ks) {
        uint32_t ah[2][4], al[2][4];
        ldsm4t(ah[0], aoffh[0] + ks * 16 * 272);
        ldsm4t(ah[1], aoffh[1] + ks * 16 * 272);
        ldsm4t(al[0], aoffl[0] + ks * 16 * 272);
        ldsm4t(al[1], aoffl[1] + ks * 16 * 272);
#pragma unroll
        for (int g4 = 0; g4 < 4; ++g4) {
            const int t0 = ng * 8 + 2 * g4;
            uint2 e0 = __ldg(&g_Gf[(ks * 16 + t0) * 32 + lane]);
            uint2 e1 = __ldg(&g_Gf[(ks * 16 + t0 + 1) * 32 + lane]);
#pragma unroll
            for (int mt = 0; mt < 2; ++mt) {
                mma_f16(acc[mt][2*g4],   ah[mt], e0.x, e0.y);
                mma_f16(acc[mt][2*g4+1], ah[mt], e1.x, e1.y);
                mma_f16(acc[mt][2*g4],   al[mt], e0.x, e0.y);
                mma_f16(acc[mt][2*g4+1], al[mt], e1.x, e1.y);
            }
        }
    }

    float p[2][2];
#pragma unroll
    for (int mt = 0; mt < 2; ++mt) { p[mt][0] = 0.0f; p[mt][1] = 0.0f; }
#pragma unroll
    for (int nt = 0; nt < 8; ++nt) {
        int c = ng * 64 + nt * 8 + 2 * (lane & 3);
        float bx = sBias[c], by = sBias[c + 1];
#pragma unroll
        for (int mt = 0; mt < 2; ++mt) {
            acc[mt][nt][0] += bx; acc[mt][nt][1] += by;
            acc[mt][nt][2] += bx; acc[mt][nt][3] += by;
            p[mt][0] += acc[mt][nt][0]*acc[mt][nt][0] + acc[mt][nt][1]*acc[mt][nt][1];
            p[mt][1] += acc[mt][nt][2]*acc[mt][nt][2] + acc[mt][nt][3]*acc[mt][nt][3];
        }
    }
#pragma unroll
    for (int mt = 0; mt < 2; ++mt) {
#pragma unroll
        for (int h = 0; h < 2; ++h) {   // quad-local reduction ONLY
            p[mt][h] += __shfl_xor_sync(0xffffffffu, p[mt][h], 1);
            p[mt][h] += __shfl_xor_sync(0xffffffffu, p[mt][h], 2);
        }
        if ((lane & 3) == 0) {
            int r0 = mg * 32 + mt * 16 + (lane >> 2);
            sPart[r0 * 2 + ng]       = p[mt][0];
            sPart[(r0 + 8) * 2 + ng] = p[mt][1];
        }
    }
    __syncthreads();

    float* gz = &g_z[((size_t)slot * NROWS + (size_t)b * 128) * DDIM];
    float* gn = &g_zn[(size_t)slot * NROWS + (size_t)b * 128];
#pragma unroll
    for (int mt = 0; mt < 2; ++mt) {
        int r0 = mg * 32 + mt * 16 + (lane >> 2);
        float sq0 = sPart[r0 * 2] + sPart[r0 * 2 + 1];
        float sq1 = sPart[(r0 + 8) * 2] + sPart[(r0 + 8) * 2 + 1];
        float n0 = sqrtf(fmaxf(sq0, EPS2));
        float n1 = sqrtf(fmaxf(sq1, EPS2));
        float t0 = tanhf(n0), t1 = tanhf(n1);
        float sc0 = (t0 > MAXNC ? MAXNC : t0) / n0;
        float sc1 = (t1 > MAXNC ? MAXNC : t1) / n1;
        if (ng == 0 && (lane & 3) == 0) {
            gn[r0]     = sq0 * sc0 * sc0;
            gn[r0 + 8] = sq1 * sc1 * sc1;
        }
#pragma unroll
        for (int nt = 0; nt < 8; ++nt) {
            int c = ng * 64 + nt * 8 + 2 * (lane & 3);
            *reinterpret_cast<float2*>(&gz[r0 * 128 + c]) =
                make_float2(acc[mt][nt][0] * sc0, acc[mt][nt][1] * sc0);
            *reinterpret_cast<float2*>(&gz[(r0 + 8) * 128 + c]) =
                make_float2(acc[mt][nt][2] * sc1, acc[mt][nt][3] * sc1);
        }
    }
}

// ============================================================================
// Kernel 1b: hyperbolic chain; emits fp16 hi/lo split of t0.
// ============================================================================
static __device__ __forceinline__ F4 ldz(int slot, int row, int lane) {
    float4 v = __ldg(reinterpret_cast<const float4*>(
        &g_z[((size_t)slot * NROWS + row) * DDIM + lane * 4]));
    F4 r = { v.x, v.y, v.z, v.w };
    return r;
}
static __device__ __forceinline__ float ldn(int slot, int row) {
    return __ldg(&g_zn[(size_t)slot * NROWS + row]);
}

__global__ void __launch_bounds__(256, 3)
chain_kernel(const float* __restrict__ alpha_p)
{
    const int tid  = threadIdx.x;
    const int wid  = tid >> 5;
    const int lane = tid & 31;
    const int row  = blockIdx.x * 8 + wid;

    float s = 0.0f, wv = 1.0f;
#pragma unroll
    for (int j = 13; j >= 0; --j) { s += wv; if (j > 0) wv *= DECAYF; }
    const float w0  = wv / s;
    const float w13 = 1.0f / s;
    const float invd = 1.0f / DECAYF;

    F4 za = ldz(0, row, lane);
    F4 zb = ldz(1, row, lane);
    F4 zc = ldz(2, row, lane);
    float sqa = ldn(0, row);
    float sqb = ldn(1, row);
    float sqc = ldn(2, row);

    F4 avg = {0,0,0,0};
    F4 vel0, vel1, vel2;
    float wj = w0;

#pragma unroll
    for (int j = 0; j < 14; ++j) {
        F4 vel = logmap_s(za, sqa, zb, sqb);
        avg.x += wj * vel.x; avg.y += wj * vel.y;
        avg.z += wj * vel.z; avg.w += wj * vel.w;
        if (j == 0) vel0 = vel;
        else if (j == 1) vel1 = vel;
        else if (j == 2) vel2 = vel;
        wj *= invd;
        za = zb; sqa = sqb;
        zb = zc; sqb = sqc;
        if (j + 3 < WINN) { zc = ldz(j + 3, row, lane); sqc = ldn(j + 3, row); }
    }

    const float alpha = __ldg(alpha_p);
    F4 zl = za; float sql = sqa;
#pragma unroll
    for (int k = 0; k < NPREDK; ++k) {
        F4 v = { avg.x * alpha, avg.y * alpha, avg.z * alpha, avg.w * alpha };
        F4 zn; float sqn;
        expmap_s(zl, sql, v, zn, sqn);

        float n  = sqrtf(fmaxf(sqn, EPS2));
        float sc = atanhf(fminf(n, CLIPC)) / n;
        const size_t m = (size_t)k * NROWS + row;
        uint32_t h0, h1, l0, l1;
        split4h(zn.x * sc, zn.y * sc, zn.z * sc, zn.w * sc, h0, h1, l0, l1);
        size_t off = m * DDIM + lane * 4;
        *reinterpret_cast<uint2*>(g_Ah + off) = make_uint2(h0, h1);
        *reinterpret_cast<uint2*>(g_Al + off) = make_uint2(l0, l1);

        if (k < 3) {
            F4 vn = logmap_s(zl, sql, zn, sqn);
            F4 vk = (k == 0 ? vel0 : (k == 1 ? vel1 : vel2));
            avg.x = (avg.x - w0 * vk.x) * DECAYF + w13 * vn.x;
            avg.y = (avg.y - w0 * vk.y) * DECAYF + w13 * vn.y;
            avg.z = (avg.z - w0 * vk.z) * DECAYF + w13 * vn.z;
            avg.w = (avg.w - w0 * vk.w) * DECAYF + w13 * vn.w;
        }
        zl = zn; sql = sqn;
    }
}

// ============================================================================
// Kernel 2: MLP on tensor cores, fp16 2-term split (unchanged R15 winner).
// ============================================================================
#define SM_AH 0
#define SM_AL 16384
#define MLP_SMEM 32768

__global__ void __launch_bounds__(256, 2)
mlp_mma_kernel(const float* __restrict__ b1, const float* __restrict__ b2,
               float* __restrict__ out)
{
    extern __shared__ char smem[];
    const uint32_t sbase = smem_to_u32(smem);
    const int tid  = threadIdx.x;
    const int lane = tid & 31;
    const int wid  = tid >> 5;
    const int mg   = wid >> 1;
    const int ng   = wid & 1;
    const int m0   = blockIdx.x * 64;

    {
        const uint4* gah = reinterpret_cast<const uint4*>(&g_Ah[(size_t)m0 * DDIM]);
        const uint4* gal = reinterpret_cast<const uint4*>(&g_Al[(size_t)m0 * DDIM]);
#pragma unroll
        for (int i = tid; i < 1024; i += 256) {
            int r = i >> 4, kc = i & 15;
            uint32_t off = (uint32_t)(r * 256 + ((kc * 16) ^ ((r & 7) << 4)));
            *reinterpret_cast<uint4*>(smem + SM_AH + off) = __ldg(gah + i);
            *reinterpret_cast<uint4*>(smem + SM_AL + off) = __ldg(gal + i);
        }
    }
    __syncthreads();

    const int rA = mg * 16 + (lane & 15);
    const uint32_t tmask_a = (uint32_t)((((lane >> 4) << 4)) ^ ((rA & 7) << 4));
    const uint32_t abase_h = sbase + SM_AH + rA * 256;
    const uint32_t abase_l = sbase + SM_AL + rA * 256;

    float cacc[3][4];
#pragma unroll
    for (int t = 0; t < 3; ++t)
#pragma unroll
        for (int q = 0; q < 4; ++q) cacc[t][q] = 0.0f;

#pragma unroll
    for (int nc = 0; nc < 4; ++nc) {
        float acc[8][4];
#pragma unroll
        for (int nt = 0; nt < 8; ++nt)
#pragma unroll
            for (int q = 0; q < 4; ++q) acc[nt][q] = 0.0f;

        const uint2* btab = &g_B1f[((size_t)nc * 8) * 16 * 32 + ng * 8 * 32 + lane];
#pragma unroll
        for (int ks = 0; ks < 8; ++ks) {
            const uint32_t xo = (uint32_t)(ks * 32);
            uint32_t ah[4], al[4];
            ldsm4(ah, abase_h + (xo ^ tmask_a));
            ldsm4(al, abase_l + (xo ^ tmask_a));
            const uint2* bk = btab + (size_t)ks * 16 * 32;
#pragma unroll
            for (int nt = 0; nt < 8; ++nt) {
                uint2 e = __ldg(bk + nt * 32);
                mma_f16(acc[nt], ah, e.x, e.y);
                mma_f16(acc[nt], al, e.x, e.y);
            }
        }

        const int kb0 = nc * 8 + ng * 4;
#pragma unroll
        for (int ks = 0; ks < 4; ++ks) {
            uint32_t ah[4], al[4];
#pragma unroll
            for (int half = 0; half < 2; ++half) {
                int nt = 2 * ks + half;
                int cB = ng * 64 + nt * 8 + 2 * (lane & 3);
                float2 b1v = __ldg(reinterpret_cast<const float2*>(&b1[nc * 128 + cB]));
                float h0 = fmaxf(acc[nt][0] + b1v.x, 0.0f);
                float h1 = fmaxf(acc[nt][1] + b1v.y, 0.0f);
                float h2 = fmaxf(acc[nt][2] + b1v.x, 0.0f);
                float h3 = fmaxf(acc[nt][3] + b1v.y, 0.0f);
                uint32_t p0, p1, q0, q1;
                split4h(h0, h1, h2, h3, p0, p1, q0, q1);
                ah[2*half]     = p0;
                ah[2*half + 1] = p1;
                al[2*half]     = q0;
                al[2*half + 1] = q1;
            }
#pragma unroll
            for (int t = 0; t < 3; ++t) {
                uint2 bw = __ldg(&g_W2f[((kb0 + ks) * 3 + t) * 32 + lane]);
                mma_f16(cacc[t], ah, bw.x, bw.y);
                mma_f16(cacc[t], al, bw.x, bw.y);
            }
        }
    }

    __syncthreads();
    float* P1 = reinterpret_cast<float*>(smem);
    float* Rb = reinterpret_cast<float*>(smem + 8192);
    const int r0 = mg * 16 + (lane >> 2);
    if (ng == 1) {
#pragma unroll
        for (int t = 0; t < 3; ++t) {
            int j0 = t * 8 + 2 * (lane & 3);
            P1[r0 * 26 + j0]           = cacc[t][0];
            P1[r0 * 26 + j0 + 1]       = cacc[t][1];
            P1[(r0 + 8) * 26 + j0]     = cacc[t][2];
            P1[(r0 + 8) * 26 + j0 + 1] = cacc[t][3];
        }
    }
    __syncthreads();
    if (ng == 0) {
#pragma unroll
        for (int t = 0; t < 3; ++t) {
            int j0 = t * 8 + 2 * (lane & 3);
            Rb[r0 * 26 + j0]           = cacc[t][0] + P1[r0 * 26 + j0];
            Rb[r0 * 26 + j0 + 1]       = cacc[t][1] + P1[r0 * 26 + j0 + 1];
            Rb[(r0 + 8) * 26 + j0]     = cacc[t][2] + P1[(r0 + 8) * 26 + j0];
            Rb[(r0 + 8) * 26 + j0 + 1] = cacc[t][3] + P1[(r0 + 8) * 26 + j0 + 1];
        }
    }
    __syncthreads();

    {
        const int kidx = m0 >> 14;
        const int bf0  = m0 & 16383;
        const int bb   = bf0 >> 7;
        const int f0   = bf0 & 127;
#pragma unroll
        for (int i = tid; i < 1536; i += 256) {
            int j = i >> 6, f = i & 63;
            out[((size_t)bb * 96 + kidx * 24 + j) * 128 + f0 + f] =
                Rb[f * 26 + j] + __ldg(&b2[j]);
        }
    }
}

// ============================================================================
extern "C" void kernel_launch(void* const* d_in, const int* in_sizes, int n_in,
                              void* d_out, int out_size) {
    const float* trend   = (const float*)d_in[0];
    const float* scoarse = (const float*)d_in[1];
    const float* sfine   = (const float*)d_in[2];
    const float* resid   = (const float*)d_in[3];
    const float* W_t = (const float*)d_in[4];
    const float* b_t = (const float*)d_in[5];
    const float* W_c = (const float*)d_in[6];
    const float* b_c = (const float*)d_in[7];
    const float* W_f = (const float*)d_in[8];
    const float* b_f = (const float*)d_in[9];
    const float* W_r = (const float*)d_in[10];
    const float* b_r = (const float*)d_in[11];
    const float* alpha = (const float*)d_in[12];
    const float* W1 = (const float*)d_in[13];
    const float* b1 = (const float*)d_in[14];
    const float* W2 = (const float*)d_in[15];
    const float* b2 = (const float*)d_in[16];

    cudaFuncSetAttribute(mlp_mma_kernel,
                         cudaFuncAttributeMaxDynamicSharedMemorySize, MLP_SMEM);
    cudaFuncSetAttribute(gemv_mma_kernel,
                         cudaFuncAttributeMaxDynamicSharedMemorySize, GEMV_SMEM);

    prep_kernel<<<88, 256>>>(W1, W2, W_t, W_c, W_f, W_r);
    gemv_mma_kernel<<<1920, 256, GEMV_SMEM>>>(trend, scoarse, sfine, resid,
                                              b_t, b_c, b_f, b_r);
    chain_kernel<<<NROWS / 8, 256>>>(alpha);
    mlp_mma_kernel<<<MTOT / 64, 256, MLP_SMEM>>>(b1, b2, (float*)d_out);
}